// round 1
// baseline (speedup 1.0000x reference)
#include <cuda_runtime.h>
#include <math.h>

#define BB 2
#define SS 1024
#define TT 2048
#define DD 1024
#define HH 8
#define KV 2
#define HDIM 128
#define EE 8
#define FFND 3584

#define GBM 128
#define GBN 128
#define GBK 8

// ------------------- device scratch (static, allocation-free) -------------------
__device__ float g_wq[DD * DD];
__device__ float g_wk[KV * HDIM * DD];
__device__ float g_wv[KV * HDIM * DD];
__device__ float g_wo[DD * DD];
__device__ float g_w1[EE * FFND * DD];
__device__ float g_w3[EE * FFND * DD];
__device__ float g_w2[EE * DD * FFND];
__device__ float g_xn[TT * DD];
__device__ float g_qt[TT * DD];
__device__ float g_q[TT * DD];
__device__ float g_kt[TT * KV * HDIM];
__device__ float g_kr[TT * KV * HDIM];
__device__ float g_vt[TT * KV * HDIM];
__device__ float g_vq[TT * KV * HDIM];
__device__ float g_sc[BB * HH * SS * SS];
__device__ float g_o[TT * DD];
__device__ float g_h[TT * DD];
__device__ float g_hn[TT * DD];
__device__ float g_up1[EE * TT * FFND];
__device__ float g_up3[EE * TT * FFND];
__device__ float g_moe[TT * DD];
__device__ int   g_cnt[EE];
__device__ int   g_tok[EE * TT];
__device__ float g_twt[EE * TT];

// ------------------- helpers -------------------
__device__ __forceinline__ float warp_min(float v) {
    #pragma unroll
    for (int o = 16; o; o >>= 1) v = fminf(v, __shfl_xor_sync(0xffffffffu, v, o));
    return v;
}
__device__ __forceinline__ float warp_max(float v) {
    #pragma unroll
    for (int o = 16; o; o >>= 1) v = fmaxf(v, __shfl_xor_sync(0xffffffffu, v, o));
    return v;
}
__device__ __forceinline__ float warp_sum(float v) {
    #pragma unroll
    for (int o = 16; o; o >>= 1) v += __shfl_xor_sync(0xffffffffu, v, o);
    return v;
}

// ------------------- zero -------------------
__global__ void zero_kernel(float* __restrict__ moe, int* __restrict__ cnt) {
    int i = blockIdx.x * 256 + threadIdx.x;
    if (i < TT * DD) moe[i] = 0.f;
    if (i < EE) cnt[i] = 0;
}

// ------------------- int4 group fake-quant (group = 128 contiguous) -------------------
__global__ void quant_kernel(const float* __restrict__ w, float* __restrict__ out, int ngroups) {
    int g = blockIdx.x * 8 + (threadIdx.x >> 5);
    if (g >= ngroups) return;
    int lane = threadIdx.x & 31;
    float4 v = reinterpret_cast<const float4*>(w)[(size_t)g * 32 + lane];
    float mn = fminf(fminf(v.x, v.y), fminf(v.z, v.w));
    float mx = fmaxf(fmaxf(v.x, v.y), fmaxf(v.z, v.w));
    mn = warp_min(mn); mx = warp_max(mx);
    float scale = fmaxf(mx - mn, 1e-5f) / 15.0f;
    float base = fminf(fmaxf(rintf(-mn / scale), 0.f), 15.f);
    float4 r;
    r.x = (fminf(fmaxf(rintf(v.x / scale) + base, 0.f), 15.f) - base) * scale;
    r.y = (fminf(fmaxf(rintf(v.y / scale) + base, 0.f), 15.f) - base) * scale;
    r.z = (fminf(fmaxf(rintf(v.z / scale) + base, 0.f), 15.f) - base) * scale;
    r.w = (fminf(fmaxf(rintf(v.w / scale) + base, 0.f), 15.f) - base) * scale;
    reinterpret_cast<float4*>(out)[(size_t)g * 32 + lane] = r;
}

// ------------------- rmsnorm -------------------
__global__ void rms_kernel(const float* __restrict__ x, const float* __restrict__ g,
                           float* __restrict__ o) {
    int row = blockIdx.x;
    const float* xr = x + (size_t)row * DD;
    float s = 0.f;
    for (int i = threadIdx.x; i < DD; i += 256) { float v = xr[i]; s += v * v; }
    __shared__ float sh[256];
    sh[threadIdx.x] = s; __syncthreads();
    for (int o2 = 128; o2; o2 >>= 1) {
        if (threadIdx.x < o2) sh[threadIdx.x] += sh[threadIdx.x + o2];
        __syncthreads();
    }
    float inv = rsqrtf(sh[0] * (1.0f / DD) + 1e-5f);
    float* orow = o + (size_t)row * DD;
    for (int i = threadIdx.x; i < DD; i += 256) orow[i] = xr[i] * inv * g[i];
}

// ------------------- generic NT GEMM: C = A @ B^T, 128x128x8 tiles, 8x8/thread ---
// MODE 0: plain store. MODE 1: store + residual. MODE 2: gather A rows via idx,
// M from Mptr[z]. MODE 3: M from Mptr[z], scatter-add C rows via idx with weights.
template<int MODE>
__global__ __launch_bounds__(256) void gemm_nt(
    const float* __restrict__ A, int lda, size_t strideA,
    const float* __restrict__ Bmat, int ldb, size_t strideB,
    float* __restrict__ C, int ldc, size_t strideC,
    int M, const int* __restrict__ Mptr,
    int N, int K,
    const float* __restrict__ resid,
    const int* __restrict__ idx,
    const float* __restrict__ wts)
{
    int z = blockIdx.z;
    if (Mptr) M = Mptr[z];
    int m0 = blockIdx.y * GBM;
    if (m0 >= M) return;
    int n0 = blockIdx.x * GBN;
    const float* Az = A + strideA * z;
    const float* Bz = Bmat + strideB * z;
    const int* idxz = idx ? (idx + (size_t)z * TT) : (const int*)nullptr;

    __shared__ float As[GBK][GBM];
    __shared__ float Bs[GBK][GBN];
    int t = threadIdx.x;
    int lrow = t >> 1;
    int lk = (t & 1) * 4;
    int ty = t >> 4, tx = t & 15;

    int grow = m0 + lrow;
    bool rowok = grow < M;
    const float* Arow = Az;
    if (rowok) {
        int r = (MODE == 2) ? idxz[grow] : grow;
        Arow = Az + (size_t)r * lda;
    }
    const float* Brow = Bz + (size_t)(n0 + lrow) * ldb;

    float acc[8][8] = {};
    for (int k0 = 0; k0 < K; k0 += GBK) {
        float4 av = make_float4(0.f, 0.f, 0.f, 0.f);
        if (rowok) av = *reinterpret_cast<const float4*>(Arow + k0 + lk);
        float4 bv = *reinterpret_cast<const float4*>(Brow + k0 + lk);
        As[lk + 0][lrow] = av.x; As[lk + 1][lrow] = av.y;
        As[lk + 2][lrow] = av.z; As[lk + 3][lrow] = av.w;
        Bs[lk + 0][lrow] = bv.x; Bs[lk + 1][lrow] = bv.y;
        Bs[lk + 2][lrow] = bv.z; Bs[lk + 3][lrow] = bv.w;
        __syncthreads();
        #pragma unroll
        for (int kk = 0; kk < GBK; kk++) {
            float a[8], bb[8];
            *reinterpret_cast<float4*>(&a[0]) = *reinterpret_cast<const float4*>(&As[kk][ty * 8]);
            *reinterpret_cast<float4*>(&a[4]) = *reinterpret_cast<const float4*>(&As[kk][ty * 8 + 4]);
            *reinterpret_cast<float4*>(&bb[0]) = *reinterpret_cast<const float4*>(&Bs[kk][tx * 8]);
            *reinterpret_cast<float4*>(&bb[4]) = *reinterpret_cast<const float4*>(&Bs[kk][tx * 8 + 4]);
            #pragma unroll
            for (int i = 0; i < 8; i++)
                #pragma unroll
                for (int j = 0; j < 8; j++)
                    acc[i][j] += a[i] * bb[j];
        }
        __syncthreads();
    }

    #pragma unroll
    for (int i = 0; i < 8; i++) {
        int row = m0 + ty * 8 + i;
        if (row >= M) continue;
        if (MODE == 3) {
            int tk = idxz[row];
            float w = wts[(size_t)z * TT + row];
            #pragma unroll
            for (int j = 0; j < 8; j++)
                atomicAdd(&C[(size_t)tk * ldc + n0 + tx * 8 + j], w * acc[i][j]);
        } else {
            float* Cr = C + strideC * z + (size_t)row * ldc + n0 + tx * 8;
            #pragma unroll
            for (int j = 0; j < 8; j++) {
                float v2 = acc[i][j];
                if (MODE == 1) v2 += resid[(size_t)row * ldc + n0 + tx * 8 + j];
                Cr[j] = v2;
            }
        }
    }
}

// ------------------- RoPE (q) -------------------
__global__ void rope_q_kernel(const float* __restrict__ in, float* __restrict__ out) {
    int rowid = blockIdx.x;  // t*HH + h
    int d = threadIdx.x;
    __shared__ float sh[HDIM];
    sh[d] = in[(size_t)rowid * HDIM + d];
    __syncthreads();
    int pos = (rowid / HH) & (SS - 1);
    int i = d & 63;
    float invf = expf(-13.815510557964274f * ((float)(2 * i) * (1.0f / HDIM)));
    float f = (float)pos * invf;
    float c = cosf(f), sn = sinf(f);
    float v = (d < 64) ? (sh[d] * c - sh[d + 64] * sn)
                       : (sh[d] * c + sh[d - 64] * sn);
    out[(size_t)rowid * HDIM + d] = v;
}

// ------------------- per-row (group=128) kv fake-quant, optional RoPE ----------
template<bool DOROPE>
__global__ void quant_row_kernel(const float* __restrict__ in, float* __restrict__ out) {
    int rowid = blockIdx.x;  // t*KV + kvh
    int d = threadIdx.x;
    float v = in[(size_t)rowid * HDIM + d];
    __shared__ float smn[HDIM], smx[HDIM], sh[HDIM];
    smn[d] = v; smx[d] = v; __syncthreads();
    for (int o2 = 64; o2; o2 >>= 1) {
        if (d < o2) {
            smn[d] = fminf(smn[d], smn[d + o2]);
            smx[d] = fmaxf(smx[d], smx[d + o2]);
        }
        __syncthreads();
    }
    float scale = fmaxf(smx[0] - smn[0], 1e-5f) / 15.0f;
    float base = fminf(fmaxf(rintf(-smn[0] / scale), 0.f), 15.f);
    float q = (fminf(fmaxf(rintf(v / scale) + base, 0.f), 15.f) - base) * scale;
    if (DOROPE) {
        sh[d] = q; __syncthreads();
        int pos = (rowid / KV) & (SS - 1);
        int i = d & 63;
        float invf = expf(-13.815510557964274f * ((float)(2 * i) * (1.0f / HDIM)));
        float f = (float)pos * invf;
        float c = cosf(f), sn = sinf(f);
        q = (d < 64) ? (sh[d] * c - sh[d + 64] * sn)
                     : (sh[d] * c + sh[d - 64] * sn);
    }
    out[(size_t)rowid * HDIM + d] = q;
}

// ------------------- attention scores: S = q k^T / sqrt(HD), causal block skip --
__global__ __launch_bounds__(256) void attn_scores_kernel(
    const float* __restrict__ q, const float* __restrict__ k, float* __restrict__ sc)
{
    int z = blockIdx.z;
    int m0 = blockIdx.y * GBM, n0 = blockIdx.x * GBN;
    if (n0 >= m0 + GBM) return;  // fully above diagonal -> never read by softmax
    int b = z >> 3, h = z & 7;
    const float* A = q + ((size_t)b * SS * HH + h) * HDIM;
    const float* Bp = k + ((size_t)b * SS * KV + (h >> 2)) * HDIM;
    float* C = sc + (size_t)z * SS * SS;

    __shared__ float As[GBK][GBM], Bs[GBK][GBN];
    int t = threadIdx.x;
    int lrow = t >> 1, lk = (t & 1) * 4;
    int ty = t >> 4, tx = t & 15;
    const float* Arow = A + (size_t)(m0 + lrow) * (HH * HDIM);
    const float* Brow = Bp + (size_t)(n0 + lrow) * (KV * HDIM);
    float acc[8][8] = {};
    for (int k0 = 0; k0 < HDIM; k0 += GBK) {
        float4 av = *reinterpret_cast<const float4*>(Arow + k0 + lk);
        float4 bv = *reinterpret_cast<const float4*>(Brow + k0 + lk);
        As[lk + 0][lrow] = av.x; As[lk + 1][lrow] = av.y;
        As[lk + 2][lrow] = av.z; As[lk + 3][lrow] = av.w;
        Bs[lk + 0][lrow] = bv.x; Bs[lk + 1][lrow] = bv.y;
        Bs[lk + 2][lrow] = bv.z; Bs[lk + 3][lrow] = bv.w;
        __syncthreads();
        #pragma unroll
        for (int kk = 0; kk < GBK; kk++) {
            float a[8], bb[8];
            *reinterpret_cast<float4*>(&a[0]) = *reinterpret_cast<const float4*>(&As[kk][ty * 8]);
            *reinterpret_cast<float4*>(&a[4]) = *reinterpret_cast<const float4*>(&As[kk][ty * 8 + 4]);
            *reinterpret_cast<float4*>(&bb[0]) = *reinterpret_cast<const float4*>(&Bs[kk][tx * 8]);
            *reinterpret_cast<float4*>(&bb[4]) = *reinterpret_cast<const float4*>(&Bs[kk][tx * 8 + 4]);
            #pragma unroll
            for (int i = 0; i < 8; i++)
                #pragma unroll
                for (int j = 0; j < 8; j++)
                    acc[i][j] += a[i] * bb[j];
        }
        __syncthreads();
    }
    const float scalef = 0.08838834764831845f;  // 1/sqrt(128)
    #pragma unroll
    for (int i = 0; i < 8; i++) {
        int row = m0 + ty * 8 + i;
        float* Cr = C + (size_t)row * SS + n0 + tx * 8;
        #pragma unroll
        for (int j = 0; j < 8; j++) Cr[j] = acc[i][j] * scalef;
    }
}

// ------------------- causal softmax (reads only c<=s; zeros c>s) ---------------
__global__ void softmax_kernel(float* __restrict__ sc) {
    int r = blockIdx.x;
    int s = r & (SS - 1);
    float* row = sc + (size_t)r * SS;
    int n = s + 1;
    __shared__ float sh[256];
    float m = -INFINITY;
    for (int i = threadIdx.x; i < n; i += 256) m = fmaxf(m, row[i]);
    sh[threadIdx.x] = m; __syncthreads();
    for (int o2 = 128; o2; o2 >>= 1) {
        if (threadIdx.x < o2) sh[threadIdx.x] = fmaxf(sh[threadIdx.x], sh[threadIdx.x + o2]);
        __syncthreads();
    }
    m = sh[0]; __syncthreads();
    float sum = 0.f;
    for (int i = threadIdx.x; i < n; i += 256) {
        float e = expf(row[i] - m);
        row[i] = e; sum += e;
    }
    sh[threadIdx.x] = sum; __syncthreads();
    for (int o2 = 128; o2; o2 >>= 1) {
        if (threadIdx.x < o2) sh[threadIdx.x] += sh[threadIdx.x + o2];
        __syncthreads();
    }
    float inv = 1.0f / sh[0];
    for (int i = threadIdx.x; i < SS; i += 256)
        row[i] = (i < n) ? row[i] * inv : 0.f;
}

// ------------------- AV (NN gemm, K bounded by causal diag) --------------------
__global__ __launch_bounds__(256) void attn_av_kernel(
    const float* __restrict__ p, const float* __restrict__ v, float* __restrict__ o)
{
    int z = blockIdx.z;
    int b = z >> 3, h = z & 7;
    int m0 = blockIdx.y * GBM;
    const float* A = p + (size_t)z * SS * SS;
    const float* V = v + ((size_t)b * SS * KV + (h >> 2)) * HDIM;

    __shared__ float As[GBK][GBM], Bs[GBK][GBN];
    int t = threadIdx.x;
    int lrow = t >> 1, lk = (t & 1) * 4;
    int bk = t >> 5, bn = (t & 31) * 4;
    int ty = t >> 4, tx = t & 15;
    float acc[8][8] = {};
    int kend = m0 + GBM;  // rows <= m0+127 need k <= row < kend
    for (int k0 = 0; k0 < kend; k0 += GBK) {
        float4 av = *reinterpret_cast<const float4*>(A + (size_t)(m0 + lrow) * SS + k0 + lk);
        As[lk + 0][lrow] = av.x; As[lk + 1][lrow] = av.y;
        As[lk + 2][lrow] = av.z; As[lk + 3][lrow] = av.w;
        float4 bv = *reinterpret_cast<const float4*>(V + (size_t)(k0 + bk) * (KV * HDIM) + bn);
        *reinterpret_cast<float4*>(&Bs[bk][bn]) = bv;
        __syncthreads();
        #pragma unroll
        for (int kk = 0; kk < GBK; kk++) {
            float a[8], bb[8];
            *reinterpret_cast<float4*>(&a[0]) = *reinterpret_cast<const float4*>(&As[kk][ty * 8]);
            *reinterpret_cast<float4*>(&a[4]) = *reinterpret_cast<const float4*>(&As[kk][ty * 8 + 4]);
            *reinterpret_cast<float4*>(&bb[0]) = *reinterpret_cast<const float4*>(&Bs[kk][tx * 8]);
            *reinterpret_cast<float4*>(&bb[4]) = *reinterpret_cast<const float4*>(&Bs[kk][tx * 8 + 4]);
            #pragma unroll
            for (int i = 0; i < 8; i++)
                #pragma unroll
                for (int j = 0; j < 8; j++)
                    acc[i][j] += a[i] * bb[j];
        }
        __syncthreads();
    }
    #pragma unroll
    for (int i = 0; i < 8; i++) {
        int row = m0 + ty * 8 + i;
        float* Or = o + ((size_t)(b * SS + row) * HH + h) * HDIM + tx * 8;
        #pragma unroll
        for (int j = 0; j < 8; j++) Or[j] = acc[i][j];
    }
}

// ------------------- router: softmax over 8, top-2, append to expert lists -----
__global__ __launch_bounds__(256) void router_kernel(
    const float* __restrict__ hn, const float* __restrict__ wg)
{
    int tkn = blockIdx.x;
    int w = threadIdx.x >> 5, lane = threadIdx.x & 31;
    const float* x = hn + (size_t)tkn * DD;
    const float* g = wg + (size_t)w * DD;
    float s = 0.f;
    for (int i = lane; i < DD; i += 32) s += x[i] * g[i];
    s = warp_sum(s);
    __shared__ float lg[EE];
    if (lane == 0) lg[w] = s;
    __syncthreads();
    if (threadIdx.x == 0) {
        float m = -INFINITY;
        #pragma unroll
        for (int e = 0; e < EE; e++) m = fmaxf(m, lg[e]);
        float ex[EE];
        #pragma unroll
        for (int e = 0; e < EE; e++) ex[e] = expf(lg[e] - m);
        int i1 = 0; float m1 = ex[0];
        #pragma unroll
        for (int e = 1; e < EE; e++) if (ex[e] > m1) { m1 = ex[e]; i1 = e; }
        int i2 = -1; float m2 = -1.f;
        #pragma unroll
        for (int e = 0; e < EE; e++) if (e != i1 && ex[e] > m2) { m2 = ex[e]; i2 = e; }
        float inv = 1.0f / (m1 + m2);
        int p1 = atomicAdd(&g_cnt[i1], 1);
        g_tok[i1 * TT + p1] = tkn; g_twt[i1 * TT + p1] = m1 * inv;
        int p2 = atomicAdd(&g_cnt[i2], 1);
        g_tok[i2 * TT + p2] = tkn; g_twt[i2 * TT + p2] = m2 * inv;
    }
}

// ------------------- silu(up1) * up3 -> up1 (valid slots only) -----------------
__global__ void silu_mul_kernel(float* __restrict__ up1, const float* __restrict__ up3,
                                const int* __restrict__ cnt) {
    int e = blockIdx.z;
    int slot = blockIdx.y;
    if (slot >= cnt[e]) return;
    size_t base = ((size_t)e * TT + slot) * FFND;
    int i = blockIdx.x * 256 + threadIdx.x;
    float a = up1[base + i], b = up3[base + i];
    up1[base + i] = (a / (1.f + expf(-a))) * b;
}

// ------------------- final: out = h + moe -------------------
__global__ void final_add_kernel(const float* __restrict__ h, const float* __restrict__ moe,
                                 float* __restrict__ out) {
    int i = blockIdx.x * 256 + threadIdx.x;
    out[i] = h[i] + moe[i];
}

// ======================= host =======================
extern "C" void kernel_launch(void* const* d_in, const int* in_sizes, int n_in,
                              void* d_out, int out_size) {
    const float* hidden = (const float*)d_in[0];
    const float* w_q    = (const float*)d_in[1];
    const float* w_k    = (const float*)d_in[2];
    const float* w_v    = (const float*)d_in[3];
    const float* w_o    = (const float*)d_in[4];
    const float* g1     = (const float*)d_in[5];
    const float* g2     = (const float*)d_in[6];
    const float* w_gate = (const float*)d_in[7];
    const float* w1     = (const float*)d_in[8];
    const float* w3     = (const float*)d_in[9];
    const float* w2     = (const float*)d_in[10];
    float* out = (float*)d_out;

    float *p_wq, *p_wk, *p_wv, *p_wo, *p_w1, *p_w3, *p_w2;
    float *p_xn, *p_qt, *p_q, *p_kt, *p_kr, *p_vt, *p_vq, *p_sc, *p_o, *p_h, *p_hn;
    float *p_up1, *p_up3, *p_moe, *p_twt;
    int *p_cnt, *p_tok;
    cudaGetSymbolAddress((void**)&p_wq, g_wq);
    cudaGetSymbolAddress((void**)&p_wk, g_wk);
    cudaGetSymbolAddress((void**)&p_wv, g_wv);
    cudaGetSymbolAddress((void**)&p_wo, g_wo);
    cudaGetSymbolAddress((void**)&p_w1, g_w1);
    cudaGetSymbolAddress((void**)&p_w3, g_w3);
    cudaGetSymbolAddress((void**)&p_w2, g_w2);
    cudaGetSymbolAddress((void**)&p_xn, g_xn);
    cudaGetSymbolAddress((void**)&p_qt, g_qt);
    cudaGetSymbolAddress((void**)&p_q, g_q);
    cudaGetSymbolAddress((void**)&p_kt, g_kt);
    cudaGetSymbolAddress((void**)&p_kr, g_kr);
    cudaGetSymbolAddress((void**)&p_vt, g_vt);
    cudaGetSymbolAddress((void**)&p_vq, g_vq);
    cudaGetSymbolAddress((void**)&p_sc, g_sc);
    cudaGetSymbolAddress((void**)&p_o, g_o);
    cudaGetSymbolAddress((void**)&p_h, g_h);
    cudaGetSymbolAddress((void**)&p_hn, g_hn);
    cudaGetSymbolAddress((void**)&p_up1, g_up1);
    cudaGetSymbolAddress((void**)&p_up3, g_up3);
    cudaGetSymbolAddress((void**)&p_moe, g_moe);
    cudaGetSymbolAddress((void**)&p_cnt, g_cnt);
    cudaGetSymbolAddress((void**)&p_tok, g_tok);
    cudaGetSymbolAddress((void**)&p_twt, g_twt);

    // zero moe accumulator + expert counts
    zero_kernel<<<8192, 256>>>(p_moe, p_cnt);

    // fake-quantize all weights (group=128, asym int4)
    quant_kernel<<<1024, 256>>>(w_q, p_wq, DD * DD / 128);
    quant_kernel<<<256, 256>>>(w_k, p_wk, KV * HDIM * DD / 128);
    quant_kernel<<<256, 256>>>(w_v, p_wv, KV * HDIM * DD / 128);
    quant_kernel<<<1024, 256>>>(w_o, p_wo, DD * DD / 128);
    quant_kernel<<<28672, 256>>>(w1, p_w1, EE * FFND * DD / 128);
    quant_kernel<<<28672, 256>>>(w3, p_w3, EE * FFND * DD / 128);
    quant_kernel<<<28672, 256>>>(w2, p_w2, EE * DD * FFND / 128);

    // attention block
    rms_kernel<<<TT, 256>>>(hidden, g1, p_xn);
    gemm_nt<0><<<dim3(8, 16, 1), 256>>>(p_xn, DD, 0, p_wq, DD, 0, p_qt, DD, 0,
                                        TT, nullptr, DD, DD, nullptr, nullptr, nullptr);
    gemm_nt<0><<<dim3(2, 16, 1), 256>>>(p_xn, DD, 0, p_wk, DD, 0, p_kt, KV * HDIM, 0,
                                        TT, nullptr, KV * HDIM, DD, nullptr, nullptr, nullptr);
    gemm_nt<0><<<dim3(2, 16, 1), 256>>>(p_xn, DD, 0, p_wv, DD, 0, p_vt, KV * HDIM, 0,
                                        TT, nullptr, KV * HDIM, DD, nullptr, nullptr, nullptr);
    rope_q_kernel<<<TT * HH, HDIM>>>(p_qt, p_q);
    quant_row_kernel<true><<<TT * KV, HDIM>>>(p_kt, p_kr);   // k: quant then rope
    quant_row_kernel<false><<<TT * KV, HDIM>>>(p_vt, p_vq);  // v: quant only
    attn_scores_kernel<<<dim3(8, 8, BB * HH), 256>>>(p_q, p_kr, p_sc);
    softmax_kernel<<<BB * HH * SS, 256>>>(p_sc);
    attn_av_kernel<<<dim3(1, 8, BB * HH), 256>>>(p_sc, p_vq, p_o);
    gemm_nt<1><<<dim3(8, 16, 1), 256>>>(p_o, DD, 0, p_wo, DD, 0, p_h, DD, 0,
                                        TT, nullptr, DD, DD, hidden, nullptr, nullptr);

    // MoE block
    rms_kernel<<<TT, 256>>>(p_h, g2, p_hn);
    router_kernel<<<TT, 256>>>(p_hn, w_gate);
    gemm_nt<2><<<dim3(28, 16, EE), 256>>>(p_hn, DD, 0, p_w1, DD, (size_t)FFND * DD,
                                          p_up1, FFND, (size_t)TT * FFND,
                                          0, p_cnt, FFND, DD, nullptr, p_tok, nullptr);
    gemm_nt<2><<<dim3(28, 16, EE), 256>>>(p_hn, DD, 0, p_w3, DD, (size_t)FFND * DD,
                                          p_up3, FFND, (size_t)TT * FFND,
                                          0, p_cnt, FFND, DD, nullptr, p_tok, nullptr);
    silu_mul_kernel<<<dim3(FFND / 256, TT, EE), 256>>>(p_up1, p_up3, p_cnt);
    gemm_nt<3><<<dim3(8, 16, EE), 256>>>(p_up1, FFND, (size_t)TT * FFND,
                                         p_w2, FFND, (size_t)DD * FFND,
                                         p_moe, DD, 0,
                                         0, p_cnt, DD, FFND, nullptr, p_tok, p_twt);
    final_add_kernel<<<8192, 256>>>(p_h, p_moe, out);
}

// round 2
// speedup vs baseline: 1.0014x; 1.0014x over previous
#include <cuda_runtime.h>
#include <math.h>

#define BB 2
#define SS 1024
#define TT 2048
#define DD 1024
#define HH 8
#define KV 2
#define HDIM 128
#define EE 8
#define FFND 3584

#define GBM 128
#define GBN 128
#define GBK 8

// ------------------- device scratch (static, allocation-free) -------------------
__device__ float g_wq[DD * DD];
__device__ float g_wk[KV * HDIM * DD];
__device__ float g_wv[KV * HDIM * DD];
__device__ float g_wo[DD * DD];
__device__ float g_w1[EE * FFND * DD];
__device__ float g_w3[EE * FFND * DD];
__device__ float g_w2[EE * DD * FFND];
__device__ float g_xn[TT * DD];
__device__ float g_qt[TT * DD];
__device__ float g_q[TT * DD];
__device__ float g_kt[TT * KV * HDIM];
__device__ float g_kr[TT * KV * HDIM];
__device__ float g_vt[TT * KV * HDIM];
__device__ float g_vq[TT * KV * HDIM];
__device__ float g_sc[BB * HH * SS * SS];
__device__ float g_o[TT * DD];
__device__ float g_h[TT * DD];
__device__ float g_hn[TT * DD];
__device__ float g_up1[EE * TT * FFND];
__device__ float g_up3[EE * TT * FFND];
__device__ float g_moe[TT * DD];
__device__ int   g_cnt[EE];
__device__ int   g_tok[EE * TT];
__device__ float g_twt[EE * TT];

// ------------------- helpers -------------------
__device__ __forceinline__ float warp_min(float v) {
    #pragma unroll
    for (int o = 16; o; o >>= 1) v = fminf(v, __shfl_xor_sync(0xffffffffu, v, o));
    return v;
}
__device__ __forceinline__ float warp_max(float v) {
    #pragma unroll
    for (int o = 16; o; o >>= 1) v = fmaxf(v, __shfl_xor_sync(0xffffffffu, v, o));
    return v;
}
__device__ __forceinline__ float warp_sum(float v) {
    #pragma unroll
    for (int o = 16; o; o >>= 1) v += __shfl_xor_sync(0xffffffffu, v, o);
    return v;
}

// ------------------- zero -------------------
__global__ void zero_kernel(float* __restrict__ moe, int* __restrict__ cnt) {
    int i = blockIdx.x * 256 + threadIdx.x;
    if (i < TT * DD) moe[i] = 0.f;
    if (i < EE) cnt[i] = 0;
}

// ------------------- int4 group fake-quant (group = 128 contiguous) -------------------
__global__ void quant_kernel(const float* __restrict__ w, float* __restrict__ out, int ngroups) {
    int g = blockIdx.x * 8 + (threadIdx.x >> 5);
    if (g >= ngroups) return;
    int lane = threadIdx.x & 31;
    float4 v = reinterpret_cast<const float4*>(w)[(size_t)g * 32 + lane];
    float mn = fminf(fminf(v.x, v.y), fminf(v.z, v.w));
    float mx = fmaxf(fmaxf(v.x, v.y), fmaxf(v.z, v.w));
    mn = warp_min(mn); mx = warp_max(mx);
    float scale = fmaxf(mx - mn, 1e-5f) / 15.0f;
    float base = fminf(fmaxf(rintf(-mn / scale), 0.f), 15.f);
    float4 r;
    r.x = (fminf(fmaxf(rintf(v.x / scale) + base, 0.f), 15.f) - base) * scale;
    r.y = (fminf(fmaxf(rintf(v.y / scale) + base, 0.f), 15.f) - base) * scale;
    r.z = (fminf(fmaxf(rintf(v.z / scale) + base, 0.f), 15.f) - base) * scale;
    r.w = (fminf(fmaxf(rintf(v.w / scale) + base, 0.f), 15.f) - base) * scale;
    reinterpret_cast<float4*>(out)[(size_t)g * 32 + lane] = r;
}

// ------------------- rmsnorm -------------------
__global__ void rms_kernel(const float* __restrict__ x, const float* __restrict__ g,
                           float* __restrict__ o) {
    int row = blockIdx.x;
    const float* xr = x + (size_t)row * DD;
    float s = 0.f;
    for (int i = threadIdx.x; i < DD; i += 256) { float v = xr[i]; s += v * v; }
    __shared__ float sh[256];
    sh[threadIdx.x] = s; __syncthreads();
    for (int o2 = 128; o2; o2 >>= 1) {
        if (threadIdx.x < o2) sh[threadIdx.x] += sh[threadIdx.x + o2];
        __syncthreads();
    }
    float inv = rsqrtf(sh[0] * (1.0f / DD) + 1e-5f);
    float* orow = o + (size_t)row * DD;
    for (int i = threadIdx.x; i < DD; i += 256) orow[i] = xr[i] * inv * g[i];
}

// ------------------- generic NT GEMM: C = A @ B^T, 128x128x8 tiles, 8x8/thread ---
// MODE 0: plain store. MODE 1: store + residual. MODE 2: gather A rows via idx,
// M from Mptr[z]. MODE 3: M from Mptr[z], scatter-add C rows via idx with weights.
template<int MODE>
__global__ __launch_bounds__(256) void gemm_nt(
    const float* __restrict__ A, int lda, size_t strideA,
    const float* __restrict__ Bmat, int ldb, size_t strideB,
    float* __restrict__ C, int ldc, size_t strideC,
    int M, const int* __restrict__ Mptr,
    int N, int K,
    const float* __restrict__ resid,
    const int* __restrict__ idx,
    const float* __restrict__ wts)
{
    int z = blockIdx.z;
    if (Mptr) M = Mptr[z];
    int m0 = blockIdx.y * GBM;
    if (m0 >= M) return;
    int n0 = blockIdx.x * GBN;
    const float* Az = A + strideA * z;
    const float* Bz = Bmat + strideB * z;
    const int* idxz = idx ? (idx + (size_t)z * TT) : (const int*)nullptr;

    __shared__ float As[GBK][GBM];
    __shared__ float Bs[GBK][GBN];
    int t = threadIdx.x;
    int lrow = t >> 1;
    int lk = (t & 1) * 4;
    int ty = t >> 4, tx = t & 15;

    int grow = m0 + lrow;
    bool rowok = grow < M;
    const float* Arow = Az;
    if (rowok) {
        int r = (MODE == 2) ? idxz[grow] : grow;
        Arow = Az + (size_t)r * lda;
    }
    const float* Brow = Bz + (size_t)(n0 + lrow) * ldb;

    float acc[8][8] = {};
    for (int k0 = 0; k0 < K; k0 += GBK) {
        float4 av = make_float4(0.f, 0.f, 0.f, 0.f);
        if (rowok) av = *reinterpret_cast<const float4*>(Arow + k0 + lk);
        float4 bv = *reinterpret_cast<const float4*>(Brow + k0 + lk);
        As[lk + 0][lrow] = av.x; As[lk + 1][lrow] = av.y;
        As[lk + 2][lrow] = av.z; As[lk + 3][lrow] = av.w;
        Bs[lk + 0][lrow] = bv.x; Bs[lk + 1][lrow] = bv.y;
        Bs[lk + 2][lrow] = bv.z; Bs[lk + 3][lrow] = bv.w;
        __syncthreads();
        #pragma unroll
        for (int kk = 0; kk < GBK; kk++) {
            float a[8], bb[8];
            *reinterpret_cast<float4*>(&a[0]) = *reinterpret_cast<const float4*>(&As[kk][ty * 8]);
            *reinterpret_cast<float4*>(&a[4]) = *reinterpret_cast<const float4*>(&As[kk][ty * 8 + 4]);
            *reinterpret_cast<float4*>(&bb[0]) = *reinterpret_cast<const float4*>(&Bs[kk][tx * 8]);
            *reinterpret_cast<float4*>(&bb[4]) = *reinterpret_cast<const float4*>(&Bs[kk][tx * 8 + 4]);
            #pragma unroll
            for (int i = 0; i < 8; i++)
                #pragma unroll
                for (int j = 0; j < 8; j++)
                    acc[i][j] += a[i] * bb[j];
        }
        __syncthreads();
    }

    #pragma unroll
    for (int i = 0; i < 8; i++) {
        int row = m0 + ty * 8 + i;
        if (row >= M) continue;
        if (MODE == 3) {
            int tk = idxz[row];
            float w = wts[(size_t)z * TT + row];
            #pragma unroll
            for (int j = 0; j < 8; j++)
                atomicAdd(&C[(size_t)tk * ldc + n0 + tx * 8 + j], w * acc[i][j]);
        } else {
            float* Cr = C + strideC * z + (size_t)row * ldc + n0 + tx * 8;
            #pragma unroll
            for (int j = 0; j < 8; j++) {
                float v2 = acc[i][j];
                if (MODE == 1) v2 += resid[(size_t)row * ldc + n0 + tx * 8 + j];
                Cr[j] = v2;
            }
        }
    }
}

// ------------------- RoPE (q) -------------------
__global__ void rope_q_kernel(const float* __restrict__ in, float* __restrict__ out) {
    int rowid = blockIdx.x;  // t*HH + h
    int d = threadIdx.x;
    __shared__ float sh[HDIM];
    sh[d] = in[(size_t)rowid * HDIM + d];
    __syncthreads();
    int pos = (rowid / HH) & (SS - 1);
    int i = d & 63;
    float invf = expf(-13.815510557964274f * ((float)(2 * i) * (1.0f / HDIM)));
    float f = (float)pos * invf;
    float c = cosf(f), sn = sinf(f);
    float v = (d < 64) ? (sh[d] * c - sh[d + 64] * sn)
                       : (sh[d] * c + sh[d - 64] * sn);
    out[(size_t)rowid * HDIM + d] = v;
}

// ------------------- per-row (group=128) kv fake-quant, optional RoPE ----------
template<bool DOROPE>
__global__ void quant_row_kernel(const float* __restrict__ in, float* __restrict__ out) {
    int rowid = blockIdx.x;  // t*KV + kvh
    int d = threadIdx.x;
    float v = in[(size_t)rowid * HDIM + d];
    __shared__ float smn[HDIM], smx[HDIM], sh[HDIM];
    smn[d] = v; smx[d] = v; __syncthreads();
    for (int o2 = 64; o2; o2 >>= 1) {
        if (d < o2) {
            smn[d] = fminf(smn[d], smn[d + o2]);
            smx[d] = fmaxf(smx[d], smx[d + o2]);
        }
        __syncthreads();
    }
    float scale = fmaxf(smx[0] - smn[0], 1e-5f) / 15.0f;
    float base = fminf(fmaxf(rintf(-smn[0] / scale), 0.f), 15.f);
    float q = (fminf(fmaxf(rintf(v / scale) + base, 0.f), 15.f) - base) * scale;
    if (DOROPE) {
        sh[d] = q; __syncthreads();
        int pos = (rowid / KV) & (SS - 1);
        int i = d & 63;
        float invf = expf(-13.815510557964274f * ((float)(2 * i) * (1.0f / HDIM)));
        float f = (float)pos * invf;
        float c = cosf(f), sn = sinf(f);
        q = (d < 64) ? (sh[d] * c - sh[d + 64] * sn)
                     : (sh[d] * c + sh[d - 64] * sn);
    }
    out[(size_t)rowid * HDIM + d] = q;
}

// ------------------- attention scores: S = q k^T / sqrt(HD), causal block skip --
__global__ __launch_bounds__(256) void attn_scores_kernel(
    const float* __restrict__ q, const float* __restrict__ k, float* __restrict__ sc)
{
    int z = blockIdx.z;
    int m0 = blockIdx.y * GBM, n0 = blockIdx.x * GBN;
    if (n0 >= m0 + GBM) return;  // fully above diagonal -> never read by softmax
    int b = z >> 3, h = z & 7;
    const float* A = q + ((size_t)b * SS * HH + h) * HDIM;
    const float* Bp = k + ((size_t)b * SS * KV + (h >> 2)) * HDIM;
    float* C = sc + (size_t)z * SS * SS;

    __shared__ float As[GBK][GBM], Bs[GBK][GBN];
    int t = threadIdx.x;
    int lrow = t >> 1, lk = (t & 1) * 4;
    int ty = t >> 4, tx = t & 15;
    const float* Arow = A + (size_t)(m0 + lrow) * (HH * HDIM);
    const float* Brow = Bp + (size_t)(n0 + lrow) * (KV * HDIM);
    float acc[8][8] = {};
    for (int k0 = 0; k0 < HDIM; k0 += GBK) {
        float4 av = *reinterpret_cast<const float4*>(Arow + k0 + lk);
        float4 bv = *reinterpret_cast<const float4*>(Brow + k0 + lk);
        As[lk + 0][lrow] = av.x; As[lk + 1][lrow] = av.y;
        As[lk + 2][lrow] = av.z; As[lk + 3][lrow] = av.w;
        Bs[lk + 0][lrow] = bv.x; Bs[lk + 1][lrow] = bv.y;
        Bs[lk + 2][lrow] = bv.z; Bs[lk + 3][lrow] = bv.w;
        __syncthreads();
        #pragma unroll
        for (int kk = 0; kk < GBK; kk++) {
            float a[8], bb[8];
            *reinterpret_cast<float4*>(&a[0]) = *reinterpret_cast<const float4*>(&As[kk][ty * 8]);
            *reinterpret_cast<float4*>(&a[4]) = *reinterpret_cast<const float4*>(&As[kk][ty * 8 + 4]);
            *reinterpret_cast<float4*>(&bb[0]) = *reinterpret_cast<const float4*>(&Bs[kk][tx * 8]);
            *reinterpret_cast<float4*>(&bb[4]) = *reinterpret_cast<const float4*>(&Bs[kk][tx * 8 + 4]);
            #pragma unroll
            for (int i = 0; i < 8; i++)
                #pragma unroll
                for (int j = 0; j < 8; j++)
                    acc[i][j] += a[i] * bb[j];
        }
        __syncthreads();
    }
    const float scalef = 0.08838834764831845f;  // 1/sqrt(128)
    #pragma unroll
    for (int i = 0; i < 8; i++) {
        int row = m0 + ty * 8 + i;
        float* Cr = C + (size_t)row * SS + n0 + tx * 8;
        #pragma unroll
        for (int j = 0; j < 8; j++) Cr[j] = acc[i][j] * scalef;
    }
}

// ------------------- causal softmax (reads only c<=s; zeros c>s) ---------------
__global__ void softmax_kernel(float* __restrict__ sc) {
    int r = blockIdx.x;
    int s = r & (SS - 1);
    float* row = sc + (size_t)r * SS;
    int n = s + 1;
    __shared__ float sh[256];
    float m = -INFINITY;
    for (int i = threadIdx.x; i < n; i += 256) m = fmaxf(m, row[i]);
    sh[threadIdx.x] = m; __syncthreads();
    for (int o2 = 128; o2; o2 >>= 1) {
        if (threadIdx.x < o2) sh[threadIdx.x] = fmaxf(sh[threadIdx.x], sh[threadIdx.x + o2]);
        __syncthreads();
    }
    m = sh[0]; __syncthreads();
    float sum = 0.f;
    for (int i = threadIdx.x; i < n; i += 256) {
        float e = expf(row[i] - m);
        row[i] = e; sum += e;
    }
    sh[threadIdx.x] = sum; __syncthreads();
    for (int o2 = 128; o2; o2 >>= 1) {
        if (threadIdx.x < o2) sh[threadIdx.x] += sh[threadIdx.x + o2];
        __syncthreads();
    }
    float inv = 1.0f / sh[0];
    for (int i = threadIdx.x; i < SS; i += 256)
        row[i] = (i < n) ? row[i] * inv : 0.f;
}

// ------------------- AV (NN gemm, K bounded by causal diag) --------------------
__global__ __launch_bounds__(256) void attn_av_kernel(
    const float* __restrict__ p, const float* __restrict__ v, float* __restrict__ o)
{
    int z = blockIdx.z;
    int b = z >> 3, h = z & 7;
    int m0 = blockIdx.y * GBM;
    const float* A = p + (size_t)z * SS * SS;
    const float* V = v + ((size_t)b * SS * KV + (h >> 2)) * HDIM;

    __shared__ float As[GBK][GBM], Bs[GBK][GBN];
    int t = threadIdx.x;
    int lrow = t >> 1, lk = (t & 1) * 4;
    int bk = t >> 5, bn = (t & 31) * 4;
    int ty = t >> 4, tx = t & 15;
    float acc[8][8] = {};
    int kend = m0 + GBM;  // rows <= m0+127 need k <= row < kend
    for (int k0 = 0; k0 < kend; k0 += GBK) {
        float4 av = *reinterpret_cast<const float4*>(A + (size_t)(m0 + lrow) * SS + k0 + lk);
        As[lk + 0][lrow] = av.x; As[lk + 1][lrow] = av.y;
        As[lk + 2][lrow] = av.z; As[lk + 3][lrow] = av.w;
        float4 bv = *reinterpret_cast<const float4*>(V + (size_t)(k0 + bk) * (KV * HDIM) + bn);
        *reinterpret_cast<float4*>(&Bs[bk][bn]) = bv;
        __syncthreads();
        #pragma unroll
        for (int kk = 0; kk < GBK; kk++) {
            float a[8], bb[8];
            *reinterpret_cast<float4*>(&a[0]) = *reinterpret_cast<const float4*>(&As[kk][ty * 8]);
            *reinterpret_cast<float4*>(&a[4]) = *reinterpret_cast<const float4*>(&As[kk][ty * 8 + 4]);
            *reinterpret_cast<float4*>(&bb[0]) = *reinterpret_cast<const float4*>(&Bs[kk][tx * 8]);
            *reinterpret_cast<float4*>(&bb[4]) = *reinterpret_cast<const float4*>(&Bs[kk][tx * 8 + 4]);
            #pragma unroll
            for (int i = 0; i < 8; i++)
                #pragma unroll
                for (int j = 0; j < 8; j++)
                    acc[i][j] += a[i] * bb[j];
        }
        __syncthreads();
    }
    #pragma unroll
    for (int i = 0; i < 8; i++) {
        int row = m0 + ty * 8 + i;
        float* Or = o + ((size_t)(b * SS + row) * HH + h) * HDIM + tx * 8;
        #pragma unroll
        for (int j = 0; j < 8; j++) Or[j] = acc[i][j];
    }
}

// ------------------- router: softmax over 8, top-2, append to expert lists -----
__global__ __launch_bounds__(256) void router_kernel(
    const float* __restrict__ hn, const float* __restrict__ wg)
{
    int tkn = blockIdx.x;
    int w = threadIdx.x >> 5, lane = threadIdx.x & 31;
    const float* x = hn + (size_t)tkn * DD;
    const float* g = wg + (size_t)w * DD;
    float s = 0.f;
    for (int i = lane; i < DD; i += 32) s += x[i] * g[i];
    s = warp_sum(s);
    __shared__ float lg[EE];
    if (lane == 0) lg[w] = s;
    __syncthreads();
    if (threadIdx.x == 0) {
        float m = -INFINITY;
        #pragma unroll
        for (int e = 0; e < EE; e++) m = fmaxf(m, lg[e]);
        float ex[EE];
        #pragma unroll
        for (int e = 0; e < EE; e++) ex[e] = expf(lg[e] - m);
        int i1 = 0; float m1 = ex[0];
        #pragma unroll
        for (int e = 1; e < EE; e++) if (ex[e] > m1) { m1 = ex[e]; i1 = e; }
        int i2 = -1; float m2 = -1.f;
        #pragma unroll
        for (int e = 0; e < EE; e++) if (e != i1 && ex[e] > m2) { m2 = ex[e]; i2 = e; }
        float inv = 1.0f / (m1 + m2);
        int p1 = atomicAdd(&g_cnt[i1], 1);
        g_tok[i1 * TT + p1] = tkn; g_twt[i1 * TT + p1] = m1 * inv;
        int p2 = atomicAdd(&g_cnt[i2], 1);
        g_tok[i2 * TT + p2] = tkn; g_twt[i2 * TT + p2] = m2 * inv;
    }
}

// ------------------- silu(up1) * up3 -> up1 (valid slots only) -----------------
__global__ void silu_mul_kernel(float* __restrict__ up1, const float* __restrict__ up3,
                                const int* __restrict__ cnt) {
    int e = blockIdx.z;
    int slot = blockIdx.y;
    if (slot >= cnt[e]) return;
    size_t base = ((size_t)e * TT + slot) * FFND;
    int i = blockIdx.x * 256 + threadIdx.x;
    float a = up1[base + i], b = up3[base + i];
    up1[base + i] = (a / (1.f + expf(-a))) * b;
}

// ------------------- final: out = h + moe -------------------
__global__ void final_add_kernel(const float* __restrict__ h, const float* __restrict__ moe,
                                 float* __restrict__ out) {
    int i = blockIdx.x * 256 + threadIdx.x;
    out[i] = h[i] + moe[i];
}

// ======================= host =======================
extern "C" void kernel_launch(void* const* d_in, const int* in_sizes, int n_in,
                              void* d_out, int out_size) {
    const float* hidden = (const float*)d_in[0];
    const float* w_q    = (const float*)d_in[1];
    const float* w_k    = (const float*)d_in[2];
    const float* w_v    = (const float*)d_in[3];
    const float* w_o    = (const float*)d_in[4];
    const float* g1     = (const float*)d_in[5];
    const float* g2     = (const float*)d_in[6];
    const float* w_gate = (const float*)d_in[7];
    const float* w1     = (const float*)d_in[8];
    const float* w3     = (const float*)d_in[9];
    const float* w2     = (const float*)d_in[10];
    float* out = (float*)d_out;

    float *p_wq, *p_wk, *p_wv, *p_wo, *p_w1, *p_w3, *p_w2;
    float *p_xn, *p_qt, *p_q, *p_kt, *p_kr, *p_vt, *p_vq, *p_sc, *p_o, *p_h, *p_hn;
    float *p_up1, *p_up3, *p_moe, *p_twt;
    int *p_cnt, *p_tok;
    cudaGetSymbolAddress((void**)&p_wq, g_wq);
    cudaGetSymbolAddress((void**)&p_wk, g_wk);
    cudaGetSymbolAddress((void**)&p_wv, g_wv);
    cudaGetSymbolAddress((void**)&p_wo, g_wo);
    cudaGetSymbolAddress((void**)&p_w1, g_w1);
    cudaGetSymbolAddress((void**)&p_w3, g_w3);
    cudaGetSymbolAddress((void**)&p_w2, g_w2);
    cudaGetSymbolAddress((void**)&p_xn, g_xn);
    cudaGetSymbolAddress((void**)&p_qt, g_qt);
    cudaGetSymbolAddress((void**)&p_q, g_q);
    cudaGetSymbolAddress((void**)&p_kt, g_kt);
    cudaGetSymbolAddress((void**)&p_kr, g_kr);
    cudaGetSymbolAddress((void**)&p_vt, g_vt);
    cudaGetSymbolAddress((void**)&p_vq, g_vq);
    cudaGetSymbolAddress((void**)&p_sc, g_sc);
    cudaGetSymbolAddress((void**)&p_o, g_o);
    cudaGetSymbolAddress((void**)&p_h, g_h);
    cudaGetSymbolAddress((void**)&p_hn, g_hn);
    cudaGetSymbolAddress((void**)&p_up1, g_up1);
    cudaGetSymbolAddress((void**)&p_up3, g_up3);
    cudaGetSymbolAddress((void**)&p_moe, g_moe);
    cudaGetSymbolAddress((void**)&p_cnt, g_cnt);
    cudaGetSymbolAddress((void**)&p_tok, g_tok);
    cudaGetSymbolAddress((void**)&p_twt, g_twt);

    // zero moe accumulator + expert counts
    zero_kernel<<<8192, 256>>>(p_moe, p_cnt);

    // fake-quantize all weights (group=128, asym int4)
    quant_kernel<<<1024, 256>>>(w_q, p_wq, DD * DD / 128);
    quant_kernel<<<256, 256>>>(w_k, p_wk, KV * HDIM * DD / 128);
    quant_kernel<<<256, 256>>>(w_v, p_wv, KV * HDIM * DD / 128);
    quant_kernel<<<1024, 256>>>(w_o, p_wo, DD * DD / 128);
    quant_kernel<<<28672, 256>>>(w1, p_w1, EE * FFND * DD / 128);
    quant_kernel<<<28672, 256>>>(w3, p_w3, EE * FFND * DD / 128);
    quant_kernel<<<28672, 256>>>(w2, p_w2, EE * DD * FFND / 128);

    // attention block
    rms_kernel<<<TT, 256>>>(hidden, g1, p_xn);
    gemm_nt<0><<<dim3(8, 16, 1), 256>>>(p_xn, DD, 0, p_wq, DD, 0, p_qt, DD, 0,
                                        TT, nullptr, DD, DD, nullptr, nullptr, nullptr);
    gemm_nt<0><<<dim3(2, 16, 1), 256>>>(p_xn, DD, 0, p_wk, DD, 0, p_kt, KV * HDIM, 0,
                                        TT, nullptr, KV * HDIM, DD, nullptr, nullptr, nullptr);
    gemm_nt<0><<<dim3(2, 16, 1), 256>>>(p_xn, DD, 0, p_wv, DD, 0, p_vt, KV * HDIM, 0,
                                        TT, nullptr, KV * HDIM, DD, nullptr, nullptr, nullptr);
    rope_q_kernel<<<TT * HH, HDIM>>>(p_qt, p_q);
    quant_row_kernel<true><<<TT * KV, HDIM>>>(p_kt, p_kr);   // k: quant then rope
    quant_row_kernel<false><<<TT * KV, HDIM>>>(p_vt, p_vq);  // v: quant only
    attn_scores_kernel<<<dim3(8, 8, BB * HH), 256>>>(p_q, p_kr, p_sc);
    softmax_kernel<<<BB * HH * SS, 256>>>(p_sc);
    attn_av_kernel<<<dim3(1, 8, BB * HH), 256>>>(p_sc, p_vq, p_o);
    gemm_nt<1><<<dim3(8, 16, 1), 256>>>(p_o, DD, 0, p_wo, DD, 0, p_h, DD, 0,
                                        TT, nullptr, DD, DD, hidden, nullptr, nullptr);

    // MoE block
    rms_kernel<<<TT, 256>>>(p_h, g2, p_hn);
    router_kernel<<<TT, 256>>>(p_hn, w_gate);
    gemm_nt<2><<<dim3(28, 16, EE), 256>>>(p_hn, DD, 0, p_w1, DD, (size_t)FFND * DD,
                                          p_up1, FFND, (size_t)TT * FFND,
                                          0, p_cnt, FFND, DD, nullptr, p_tok, nullptr);
    gemm_nt<2><<<dim3(28, 16, EE), 256>>>(p_hn, DD, 0, p_w3, DD, (size_t)FFND * DD,
                                          p_up3, FFND, (size_t)TT * FFND,
                                          0, p_cnt, FFND, DD, nullptr, p_tok, nullptr);
    silu_mul_kernel<<<dim3(FFND / 256, TT, EE), 256>>>(p_up1, p_up3, p_cnt);
    gemm_nt<3><<<dim3(8, 16, EE), 256>>>(p_up1, FFND, (size_t)TT * FFND,
                                         p_w2, FFND, (size_t)DD * FFND,
                                         p_moe, DD, 0,
                                         0, p_cnt, DD, FFND, nullptr, p_tok, p_twt);
    final_add_kernel<<<8192, 256>>>(p_h, p_moe, out);
}

// round 4
// speedup vs baseline: 2.4649x; 2.4614x over previous
#include <cuda_runtime.h>
#include <cuda_bf16.h>
#include <math.h>
#include <stdint.h>

#define BB 2
#define SS 1024
#define TT 2048
#define DD 1024
#define HH 8
#define KV 2
#define HDIM 128
#define EE 8
#define FFND 3584

#define KT 64
#define STAGES 3
#define TILE_BYTES 16384                 // 128 rows x 128 bytes
#define STAGE_BYTES (4 * TILE_BYTES)     // Ahi, Alo, Bhi, Blo
#define SMEM_SZ (STAGES * STAGE_BYTES)   // 192 KB

#define GBM 128
#define GBN 128
#define GBK 8

typedef __nv_bfloat16 bf16;

__device__ bf16 g_wqh[DD * DD];        __device__ bf16 g_wql[DD * DD];
__device__ bf16 g_wkh[KV * HDIM * DD]; __device__ bf16 g_wkl[KV * HDIM * DD];
__device__ bf16 g_wvh[KV * HDIM * DD]; __device__ bf16 g_wvl[KV * HDIM * DD];
__device__ bf16 g_woh[DD * DD];        __device__ bf16 g_wol[DD * DD];
__device__ bf16 g_w1h[EE * FFND * DD]; __device__ bf16 g_w1l[EE * FFND * DD];
__device__ bf16 g_w3h[EE * FFND * DD]; __device__ bf16 g_w3l[EE * FFND * DD];
__device__ bf16 g_w2h[EE * DD * FFND]; __device__ bf16 g_w2l[EE * DD * FFND];
__device__ bf16 g_xnh[TT * DD];        __device__ bf16 g_xnl[TT * DD];
__device__ bf16 g_hnh[TT * DD];        __device__ bf16 g_hnl[TT * DD];
__device__ bf16 g_oh[TT * DD];         __device__ bf16 g_ol[TT * DD];
__device__ bf16 g_uph[EE * TT * FFND]; __device__ bf16 g_upl[EE * TT * FFND];
__device__ float g_qt[TT * DD];
__device__ float g_q[TT * DD];
__device__ float g_kt[TT * KV * HDIM];
__device__ float g_kr[TT * KV * HDIM];
__device__ float g_vt[TT * KV * HDIM];
__device__ float g_vq[TT * KV * HDIM];
__device__ float g_sc[BB * HH * SS * SS];
__device__ float g_h[TT * DD];
__device__ float g_hn[TT * DD];
__device__ float g_up1[EE * TT * FFND];
__device__ float g_moe[TT * DD];
__device__ int   g_cnt[EE];
__device__ int   g_tok[EE * TT];
__device__ float g_twt[EE * TT];

// ---------------- ptx helpers (arch-agnostic: mma.sync / ldmatrix / cp.async) ---
__device__ __forceinline__ uint32_t smem_u32(const void* p) {
    uint32_t a;
    asm("{ .reg .u64 t; cvta.to.shared.u64 t, %1; cvt.u32.u64 %0, t; }" : "=r"(a) : "l"(p));
    return a;
}
__device__ __forceinline__ void ldsm4(uint32_t a, uint32_t& r0, uint32_t& r1,
                                      uint32_t& r2, uint32_t& r3) {
    asm volatile("ldmatrix.sync.aligned.m8n8.x4.shared.b16 {%0,%1,%2,%3}, [%4];"
                 : "=r"(r0), "=r"(r1), "=r"(r2), "=r"(r3) : "r"(a));
}
__device__ __forceinline__ void mma16816(float* c, const uint32_t* a, const uint32_t* b) {
    asm volatile("mma.sync.aligned.m16n8k16.row.col.f32.bf16.bf16.f32 "
                 "{%0,%1,%2,%3}, {%4,%5,%6,%7}, {%8,%9}, {%0,%1,%2,%3};"
                 : "+f"(c[0]), "+f"(c[1]), "+f"(c[2]), "+f"(c[3])
                 : "r"(a[0]), "r"(a[1]), "r"(a[2]), "r"(a[3]), "r"(b[0]), "r"(b[1]));
}
__device__ __forceinline__ void cpa16(uint32_t dst, const void* src) {
    asm volatile("cp.async.cg.shared.global [%0], [%1], 16;" :: "r"(dst), "l"(src));
}
__device__ __forceinline__ void cpa_commit() { asm volatile("cp.async.commit_group;" ::: "memory"); }
__device__ __forceinline__ void cpa_wait1() { asm volatile("cp.async.wait_group 1;" ::: "memory"); }

__device__ __forceinline__ float warp_min(float v) {
    #pragma unroll
    for (int o = 16; o; o >>= 1) v = fminf(v, __shfl_xor_sync(0xffffffffu, v, o));
    return v;
}
__device__ __forceinline__ float warp_max(float v) {
    #pragma unroll
    for (int o = 16; o; o >>= 1) v = fmaxf(v, __shfl_xor_sync(0xffffffffu, v, o));
    return v;
}
__device__ __forceinline__ float warp_sum(float v) {
    #pragma unroll
    for (int o = 16; o; o >>= 1) v += __shfl_xor_sync(0xffffffffu, v, o);
    return v;
}
__device__ __forceinline__ void split_bf(float v, bf16& h, bf16& l) {
    h = __float2bfloat16(v);
    l = __float2bfloat16(v - __bfloat162float(h));
}
__device__ __forceinline__ uint32_t swz(uint32_t off) { return off ^ ((off >> 3) & 0x70); }

// ---------------- small kernels ----------------
__global__ void zero_kernel(float* __restrict__ moe, int* __restrict__ cnt) {
    int i = blockIdx.x * 256 + threadIdx.x;
    if (i < TT * DD) moe[i] = 0.f;
    if (i < EE) cnt[i] = 0;
}

__global__ void quant_kernel(const float* __restrict__ w, bf16* __restrict__ hi,
                             bf16* __restrict__ lo, int ngroups) {
    int g = blockIdx.x * 8 + (threadIdx.x >> 5);
    if (g >= ngroups) return;
    int lane = threadIdx.x & 31;
    float4 v = reinterpret_cast<const float4*>(w)[(size_t)g * 32 + lane];
    float mn = fminf(fminf(v.x, v.y), fminf(v.z, v.w));
    float mx = fmaxf(fmaxf(v.x, v.y), fmaxf(v.z, v.w));
    mn = warp_min(mn); mx = warp_max(mx);
    float scale = fmaxf(mx - mn, 1e-5f) / 15.0f;
    float base = fminf(fmaxf(rintf(-mn / scale), 0.f), 15.f);
    float r[4] = {v.x, v.y, v.z, v.w};
    bf16 h[4], l[4];
    #pragma unroll
    for (int j = 0; j < 4; j++) {
        float q = (fminf(fmaxf(rintf(r[j] / scale) + base, 0.f), 15.f) - base) * scale;
        split_bf(q, h[j], l[j]);
    }
    size_t idx = (size_t)g * 128 + lane * 4;
    *reinterpret_cast<uint2*>(hi + idx) = *reinterpret_cast<uint2*>(h);
    *reinterpret_cast<uint2*>(lo + idx) = *reinterpret_cast<uint2*>(l);
}

template<bool WF32>
__global__ void rms_split_kernel(const float* __restrict__ x, const float* __restrict__ g,
                                 float* __restrict__ f32o, bf16* __restrict__ hi,
                                 bf16* __restrict__ lo) {
    int row = blockIdx.x;
    const float* xr = x + (size_t)row * DD;
    float s = 0.f;
    for (int i = threadIdx.x; i < DD; i += 256) { float v = xr[i]; s += v * v; }
    __shared__ float sh[256];
    sh[threadIdx.x] = s; __syncthreads();
    for (int o2 = 128; o2; o2 >>= 1) {
        if (threadIdx.x < o2) sh[threadIdx.x] += sh[threadIdx.x + o2];
        __syncthreads();
    }
    float inv = rsqrtf(sh[0] * (1.0f / DD) + 1e-5f);
    for (int i = threadIdx.x; i < DD; i += 256) {
        float v = xr[i] * inv * g[i];
        if (WF32) f32o[(size_t)row * DD + i] = v;
        bf16 h, l; split_bf(v, h, l);
        hi[(size_t)row * DD + i] = h;
        lo[(size_t)row * DD + i] = l;
    }
}

// ============ bf16x3 mma.sync GEMM: C = A @ B^T (128x128 CTA tile) ============
// MODE 0 store f32 | 1 +resid | 2 gather-A rows, M=Mptr[z] | 3 scatter-add w/ wts |
// MODE 4 gather-A, epilogue silu(resid)*acc split-> CH/CL
template<int MODE>
__global__ __launch_bounds__(256, 1) void gemm_tc(
    const bf16* __restrict__ Ahi, const bf16* __restrict__ Alo, int lda, size_t strideA,
    const bf16* __restrict__ Bhi, const bf16* __restrict__ Blo, int ldb, size_t strideB,
    float* __restrict__ C, bf16* __restrict__ CH, bf16* __restrict__ CL,
    int ldc, size_t strideC,
    int M, const int* __restrict__ Mptr, int K,
    const float* __restrict__ resid, const int* __restrict__ idx,
    const float* __restrict__ wts)
{
    int z = blockIdx.z;
    if (Mptr) M = Mptr[z];
    int m0 = blockIdx.y * 128;
    if (m0 >= M) return;
    int n0 = blockIdx.x * 128;
    int tid = threadIdx.x;
    int wid = tid >> 5, lid = tid & 31;

    extern __shared__ char smem[];
    uint32_t sb = smem_u32(smem);
    const int* idxz = (MODE >= 2) ? (idx + (size_t)z * TT) : (const int*)nullptr;

    // per-thread cp.async slots: 4096 chunks of 16B / 256 thr = 16 each
    const bf16* srcb[16];
    uint32_t dsto[16];
    #pragma unroll
    for (int ci = 0; ci < 16; ci++) {
        int gid = ci * 256 + tid;
        int t4 = gid >> 10;          // 0:Ahi 1:Alo 2:Bhi 3:Blo
        int r  = (gid >> 3) & 127;
        int c8 = gid & 7;
        const bf16* basep;
        size_t off_el;
        if (t4 < 2) {
            int row = m0 + r;
            if (row >= M) row = m0;
            int rg = (MODE == 2 || MODE == 4) ? idxz[row] : row;
            basep = (t4 == 0) ? Ahi : Alo;
            off_el = strideA * (size_t)z + (size_t)rg * lda;
        } else {
            int row = n0 + r;
            basep = (t4 == 2) ? Bhi : Blo;
            off_el = strideB * (size_t)z + (size_t)row * ldb;
        }
        srcb[ci] = basep + off_el + c8 * 8;
        dsto[ci] = (uint32_t)(t4 * TILE_BYTES) + swz((uint32_t)(r * 128 + c8 * 16));
    }

    int n_kt = K / KT;
    // prologue: 2 stages
    #pragma unroll 1
    for (int p = 0; p < STAGES - 1; p++) {
        uint32_t base = sb + p * STAGE_BYTES;
        #pragma unroll
        for (int ci = 0; ci < 16; ci++) cpa16(base + dsto[ci], srcb[ci] + (size_t)p * KT);
        cpa_commit();
    }

    // warp tiling: 4 m-bands x 2 n-bands; each warp 32x64
    int wr = (wid & 3) * 32;
    int wc = (wid >> 2) * 64;
    int rowm = (lid & 7) + ((lid >> 3) & 1) * 8;   // 0..15
    int colb = (lid >> 4) * 16;                    // 0 or 16

    float acc[2][8][4] = {};

    #pragma unroll 1
    for (int kt = 0; kt < n_kt; kt++) {
        cpa_wait1();
        __syncthreads();
        if (kt + STAGES - 1 < n_kt) {
            int sl = (kt + STAGES - 1) % STAGES;
            uint32_t base = sb + sl * STAGE_BYTES;
            #pragma unroll
            for (int ci = 0; ci < 16; ci++)
                cpa16(base + dsto[ci], srcb[ci] + (size_t)(kt + STAGES - 1) * KT);
            cpa_commit();
        }
        uint32_t sbase = sb + (kt % STAGES) * STAGE_BYTES;
        #pragma unroll
        for (int s16 = 0; s16 < 4; s16++) {
            int kb0 = s16 * 32 + colb;
            uint32_t ah[2][4], al[2][4], bh[8][2], bl[8][2];
            #pragma unroll
            for (int i = 0; i < 2; i++) {
                uint32_t off = (uint32_t)((wr + i * 16 + rowm) * 128 + kb0);
                ldsm4(sbase + swz(off), ah[i][0], ah[i][1], ah[i][2], ah[i][3]);
                ldsm4(sbase + TILE_BYTES + swz(off), al[i][0], al[i][1], al[i][2], al[i][3]);
            }
            #pragma unroll
            for (int j = 0; j < 4; j++) {
                uint32_t off = (uint32_t)((wc + j * 16 + rowm) * 128 + kb0);
                uint32_t r0, r1, r2, r3;
                ldsm4(sbase + 2 * TILE_BYTES + swz(off), r0, r1, r2, r3);
                bh[j * 2][0] = r0; bh[j * 2][1] = r2;
                bh[j * 2 + 1][0] = r1; bh[j * 2 + 1][1] = r3;
                ldsm4(sbase + 3 * TILE_BYTES + swz(off), r0, r1, r2, r3);
                bl[j * 2][0] = r0; bl[j * 2][1] = r2;
                bl[j * 2 + 1][0] = r1; bl[j * 2 + 1][1] = r3;
            }
            #pragma unroll
            for (int i = 0; i < 2; i++)
                #pragma unroll
                for (int jn = 0; jn < 8; jn++) {
                    mma16816(acc[i][jn], ah[i], bh[jn]);
                    mma16816(acc[i][jn], ah[i], bl[jn]);
                    mma16816(acc[i][jn], al[i], bh[jn]);
                }
        }
    }

    // epilogue: frag (i,jn): rows m0+wr+i*16+(lid>>2)+{0,8}, cols n0+wc+jn*8+(lid&3)*2
    #pragma unroll
    for (int i = 0; i < 2; i++) {
        #pragma unroll
        for (int jn = 0; jn < 8; jn++) {
            int r0 = m0 + wr + i * 16 + (lid >> 2);
            int cc = n0 + wc + jn * 8 + (lid & 3) * 2;
            #pragma unroll
            for (int half = 0; half < 2; half++) {
                int row = r0 + half * 8;
                if (row >= M) continue;
                float v0 = acc[i][jn][half * 2 + 0];
                float v1 = acc[i][jn][half * 2 + 1];
                if (MODE == 0 || MODE == 1 || MODE == 2) {
                    float* Cr = C + strideC * z + (size_t)row * ldc + cc;
                    if (MODE == 1) {
                        const float* rr = resid + (size_t)row * ldc + cc;
                        v0 += rr[0]; v1 += rr[1];
                    }
                    float2 st = make_float2(v0, v1);
                    *reinterpret_cast<float2*>(Cr) = st;
                } else if (MODE == 3) {
                    int tk = idxz[row];
                    float w = wts[(size_t)z * TT + row];
                    float* Cr = C + (size_t)tk * ldc + cc;
                    atomicAdd(Cr + 0, w * v0);
                    atomicAdd(Cr + 1, w * v1);
                } else {  // MODE 4
                    const float* ar = resid + strideC * z + (size_t)row * ldc + cc;
                    float a0 = ar[0], a1 = ar[1];
                    float gv0 = (a0 / (1.f + expf(-a0))) * v0;
                    float gv1 = (a1 / (1.f + expf(-a1))) * v1;
                    bf16 h0, l0, h1, l1;
                    split_bf(gv0, h0, l0); split_bf(gv1, h1, l1);
                    size_t o = strideC * z + (size_t)row * ldc + cc;
                    CH[o] = h0; CH[o + 1] = h1;
                    CL[o] = l0; CL[o + 1] = l1;
                }
            }
        }
    }
}

// ---------------- RoPE / kv quant ----------------
__global__ void rope_q_kernel(const float* __restrict__ in, float* __restrict__ out) {
    int rowid = blockIdx.x;
    int d = threadIdx.x;
    __shared__ float sh[HDIM];
    sh[d] = in[(size_t)rowid * HDIM + d];
    __syncthreads();
    int pos = (rowid / HH) & (SS - 1);
    int i = d & 63;
    float invf = expf(-13.815510557964274f * ((float)(2 * i) * (1.0f / HDIM)));
    float f = (float)pos * invf;
    float c = cosf(f), sn = sinf(f);
    float v = (d < 64) ? (sh[d] * c - sh[d + 64] * sn)
                       : (sh[d] * c + sh[d - 64] * sn);
    out[(size_t)rowid * HDIM + d] = v;
}

template<bool DOROPE>
__global__ void quant_row_kernel(const float* __restrict__ in, float* __restrict__ out) {
    int rowid = blockIdx.x;
    int d = threadIdx.x;
    float v = in[(size_t)rowid * HDIM + d];
    __shared__ float smn[HDIM], smx[HDIM], sh[HDIM];
    smn[d] = v; smx[d] = v; __syncthreads();
    for (int o2 = 64; o2; o2 >>= 1) {
        if (d < o2) {
            smn[d] = fminf(smn[d], smn[d + o2]);
            smx[d] = fmaxf(smx[d], smx[d + o2]);
        }
        __syncthreads();
    }
    float scale = fmaxf(smx[0] - smn[0], 1e-5f) / 15.0f;
    float base = fminf(fmaxf(rintf(-smn[0] / scale), 0.f), 15.f);
    float q = (fminf(fmaxf(rintf(v / scale) + base, 0.f), 15.f) - base) * scale;
    if (DOROPE) {
        sh[d] = q; __syncthreads();
        int pos = (rowid / KV) & (SS - 1);
        int i = d & 63;
        float invf = expf(-13.815510557964274f * ((float)(2 * i) * (1.0f / HDIM)));
        float f = (float)pos * invf;
        float c = cosf(f), sn = sinf(f);
        q = (d < 64) ? (sh[d] * c - sh[d + 64] * sn)
                     : (sh[d] * c + sh[d - 64] * sn);
    }
    out[(size_t)rowid * HDIM + d] = q;
}

// ---------------- attention (SIMT fp32) ----------------
__global__ __launch_bounds__(256) void attn_scores_kernel(
    const float* __restrict__ q, const float* __restrict__ k, float* __restrict__ sc)
{
    int z = blockIdx.z;
    int m0 = blockIdx.y * GBM, n0 = blockIdx.x * GBN;
    if (n0 >= m0 + GBM) return;
    int b = z >> 3, h = z & 7;
    const float* A = q + ((size_t)b * SS * HH + h) * HDIM;
    const float* Bp = k + ((size_t)b * SS * KV + (h >> 2)) * HDIM;
    float* C = sc + (size_t)z * SS * SS;

    __shared__ float As[GBK][GBM], Bs[GBK][GBN];
    int t = threadIdx.x;
    int lrow = t >> 1, lk = (t & 1) * 4;
    int ty = t >> 4, tx = t & 15;
    const float* Arow = A + (size_t)(m0 + lrow) * (HH * HDIM);
    const float* Brow = Bp + (size_t)(n0 + lrow) * (KV * HDIM);
    float acc[8][8] = {};
    for (int k0 = 0; k0 < HDIM; k0 += GBK) {
        float4 av = *reinterpret_cast<const float4*>(Arow + k0 + lk);
        float4 bv = *reinterpret_cast<const float4*>(Brow + k0 + lk);
        As[lk + 0][lrow] = av.x; As[lk + 1][lrow] = av.y;
        As[lk + 2][lrow] = av.z; As[lk + 3][lrow] = av.w;
        Bs[lk + 0][lrow] = bv.x; Bs[lk + 1][lrow] = bv.y;
        Bs[lk + 2][lrow] = bv.z; Bs[lk + 3][lrow] = bv.w;
        __syncthreads();
        #pragma unroll
        for (int kk = 0; kk < GBK; kk++) {
            float a[8], bb[8];
            *reinterpret_cast<float4*>(&a[0]) = *reinterpret_cast<const float4*>(&As[kk][ty * 8]);
            *reinterpret_cast<float4*>(&a[4]) = *reinterpret_cast<const float4*>(&As[kk][ty * 8 + 4]);
            *reinterpret_cast<float4*>(&bb[0]) = *reinterpret_cast<const float4*>(&Bs[kk][tx * 8]);
            *reinterpret_cast<float4*>(&bb[4]) = *reinterpret_cast<const float4*>(&Bs[kk][tx * 8 + 4]);
            #pragma unroll
            for (int i = 0; i < 8; i++)
                #pragma unroll
                for (int j = 0; j < 8; j++)
                    acc[i][j] += a[i] * bb[j];
        }
        __syncthreads();
    }
    const float scalef = 0.08838834764831845f;
    #pragma unroll
    for (int i = 0; i < 8; i++) {
        int row = m0 + ty * 8 + i;
        float* Cr = C + (size_t)row * SS + n0 + tx * 8;
        #pragma unroll
        for (int j = 0; j < 8; j++) Cr[j] = acc[i][j] * scalef;
    }
}

__global__ void softmax_kernel(float* __restrict__ sc) {
    int r = blockIdx.x;
    int s = r & (SS - 1);
    float* row = sc + (size_t)r * SS;
    int n = s + 1;
    __shared__ float sh[256];
    float m = -INFINITY;
    for (int i = threadIdx.x; i < n; i += 256) m = fmaxf(m, row[i]);
    sh[threadIdx.x] = m; __syncthreads();
    for (int o2 = 128; o2; o2 >>= 1) {
        if (threadIdx.x < o2) sh[threadIdx.x] = fmaxf(sh[threadIdx.x], sh[threadIdx.x + o2]);
        __syncthreads();
    }
    m = sh[0]; __syncthreads();
    float sum = 0.f;
    for (int i = threadIdx.x; i < n; i += 256) {
        float e = expf(row[i] - m);
        row[i] = e; sum += e;
    }
    sh[threadIdx.x] = sum; __syncthreads();
    for (int o2 = 128; o2; o2 >>= 1) {
        if (threadIdx.x < o2) sh[threadIdx.x] += sh[threadIdx.x + o2];
        __syncthreads();
    }
    float inv = 1.0f / sh[0];
    for (int i = threadIdx.x; i < SS; i += 256)
        row[i] = (i < n) ? row[i] * inv : 0.f;
}

__global__ __launch_bounds__(256) void attn_av_kernel(
    const float* __restrict__ p, const float* __restrict__ v,
    bf16* __restrict__ oh, bf16* __restrict__ ol)
{
    int z = blockIdx.z;
    int b = z >> 3, h = z & 7;
    int m0 = blockIdx.y * GBM;
    const float* A = p + (size_t)z * SS * SS;
    const float* V = v + ((size_t)b * SS * KV + (h >> 2)) * HDIM;

    __shared__ float As[GBK][GBM], Bs[GBK][GBN];
    int t = threadIdx.x;
    int lrow = t >> 1, lk = (t & 1) * 4;
    int bk = t >> 5, bn = (t & 31) * 4;
    int ty = t >> 4, tx = t & 15;
    float acc[8][8] = {};
    int kend = m0 + GBM;
    for (int k0 = 0; k0 < kend; k0 += GBK) {
        float4 av = *reinterpret_cast<const float4*>(A + (size_t)(m0 + lrow) * SS + k0 + lk);
        As[lk + 0][lrow] = av.x; As[lk + 1][lrow] = av.y;
        As[lk + 2][lrow] = av.z; As[lk + 3][lrow] = av.w;
        float4 bv = *reinterpret_cast<const float4*>(V + (size_t)(k0 + bk) * (KV * HDIM) + bn);
        *reinterpret_cast<float4*>(&Bs[bk][bn]) = bv;
        __syncthreads();
        #pragma unroll
        for (int kk = 0; kk < GBK; kk++) {
            float a[8], bb[8];
            *reinterpret_cast<float4*>(&a[0]) = *reinterpret_cast<const float4*>(&As[kk][ty * 8]);
            *reinterpret_cast<float4*>(&a[4]) = *reinterpret_cast<const float4*>(&As[kk][ty * 8 + 4]);
            *reinterpret_cast<float4*>(&bb[0]) = *reinterpret_cast<const float4*>(&Bs[kk][tx * 8]);
            *reinterpret_cast<float4*>(&bb[4]) = *reinterpret_cast<const float4*>(&Bs[kk][tx * 8 + 4]);
            #pragma unroll
            for (int i = 0; i < 8; i++)
                #pragma unroll
                for (int j = 0; j < 8; j++)
                    acc[i][j] += a[i] * bb[j];
        }
        __syncthreads();
    }
    #pragma unroll
    for (int i = 0; i < 8; i++) {
        int row = m0 + ty * 8 + i;
        size_t base = ((size_t)(b * SS + row) * HH + h) * HDIM + tx * 8;
        #pragma unroll
        for (int j = 0; j < 8; j++) {
            bf16 hv, lv; split_bf(acc[i][j], hv, lv);
            oh[base + j] = hv; ol[base + j] = lv;
        }
    }
}

// ---------------- router ----------------
__global__ __launch_bounds__(256) void router_kernel(
    const float* __restrict__ hn, const float* __restrict__ wg)
{
    int tkn = blockIdx.x;
    int w = threadIdx.x >> 5, lane = threadIdx.x & 31;
    const float* x = hn + (size_t)tkn * DD;
    const float* g = wg + (size_t)w * DD;
    float s = 0.f;
    for (int i = lane; i < DD; i += 32) s += x[i] * g[i];
    s = warp_sum(s);
    __shared__ float lg[EE];
    if (lane == 0) lg[w] = s;
    __syncthreads();
    if (threadIdx.x == 0) {
        float m = -INFINITY;
        #pragma unroll
        for (int e = 0; e < EE; e++) m = fmaxf(m, lg[e]);
        float ex[EE];
        #pragma unroll
        for (int e = 0; e < EE; e++) ex[e] = expf(lg[e] - m);
        int i1 = 0; float m1 = ex[0];
        #pragma unroll
        for (int e = 1; e < EE; e++) if (ex[e] > m1) { m1 = ex[e]; i1 = e; }
        int i2 = -1; float m2 = -1.f;
        #pragma unroll
        for (int e = 0; e < EE; e++) if (e != i1 && ex[e] > m2) { m2 = ex[e]; i2 = e; }
        float inv = 1.0f / (m1 + m2);
        int p1 = atomicAdd(&g_cnt[i1], 1);
        g_tok[i1 * TT + p1] = tkn; g_twt[i1 * TT + p1] = m1 * inv;
        int p2 = atomicAdd(&g_cnt[i2], 1);
        g_tok[i2 * TT + p2] = tkn; g_twt[i2 * TT + p2] = m2 * inv;
    }
}

__global__ void final_add_kernel(const float* __restrict__ h, const float* __restrict__ moe,
                                 float* __restrict__ out) {
    int i = blockIdx.x * 256 + threadIdx.x;
    out[i] = h[i] + moe[i];
}

// ======================= host =======================
extern "C" void kernel_launch(void* const* d_in, const int* in_sizes, int n_in,
                              void* d_out, int out_size) {
    const float* hidden = (const float*)d_in[0];
    const float* w_q    = (const float*)d_in[1];
    const float* w_k    = (const float*)d_in[2];
    const float* w_v    = (const float*)d_in[3];
    const float* w_o    = (const float*)d_in[4];
    const float* g1     = (const float*)d_in[5];
    const float* g2     = (const float*)d_in[6];
    const float* w_gate = (const float*)d_in[7];
    const float* w1     = (const float*)d_in[8];
    const float* w3     = (const float*)d_in[9];
    const float* w2     = (const float*)d_in[10];
    float* out = (float*)d_out;

    bf16 *p_wqh, *p_wql, *p_wkh, *p_wkl, *p_wvh, *p_wvl, *p_woh, *p_wol;
    bf16 *p_w1h, *p_w1l, *p_w3h, *p_w3l, *p_w2h, *p_w2l;
    bf16 *p_xnh, *p_xnl, *p_hnh, *p_hnl, *p_oh, *p_ol, *p_uph, *p_upl;
    float *p_qt, *p_q, *p_kt, *p_kr, *p_vt, *p_vq, *p_sc, *p_h, *p_hn, *p_up1, *p_moe, *p_twt;
    int *p_cnt, *p_tok;
    cudaGetSymbolAddress((void**)&p_wqh, g_wqh); cudaGetSymbolAddress((void**)&p_wql, g_wql);
    cudaGetSymbolAddress((void**)&p_wkh, g_wkh); cudaGetSymbolAddress((void**)&p_wkl, g_wkl);
    cudaGetSymbolAddress((void**)&p_wvh, g_wvh); cudaGetSymbolAddress((void**)&p_wvl, g_wvl);
    cudaGetSymbolAddress((void**)&p_woh, g_woh); cudaGetSymbolAddress((void**)&p_wol, g_wol);
    cudaGetSymbolAddress((void**)&p_w1h, g_w1h); cudaGetSymbolAddress((void**)&p_w1l, g_w1l);
    cudaGetSymbolAddress((void**)&p_w3h, g_w3h); cudaGetSymbolAddress((void**)&p_w3l, g_w3l);
    cudaGetSymbolAddress((void**)&p_w2h, g_w2h); cudaGetSymbolAddress((void**)&p_w2l, g_w2l);
    cudaGetSymbolAddress((void**)&p_xnh, g_xnh); cudaGetSymbolAddress((void**)&p_xnl, g_xnl);
    cudaGetSymbolAddress((void**)&p_hnh, g_hnh); cudaGetSymbolAddress((void**)&p_hnl, g_hnl);
    cudaGetSymbolAddress((void**)&p_oh, g_oh);   cudaGetSymbolAddress((void**)&p_ol, g_ol);
    cudaGetSymbolAddress((void**)&p_uph, g_uph); cudaGetSymbolAddress((void**)&p_upl, g_upl);
    cudaGetSymbolAddress((void**)&p_qt, g_qt);   cudaGetSymbolAddress((void**)&p_q, g_q);
    cudaGetSymbolAddress((void**)&p_kt, g_kt);   cudaGetSymbolAddress((void**)&p_kr, g_kr);
    cudaGetSymbolAddress((void**)&p_vt, g_vt);   cudaGetSymbolAddress((void**)&p_vq, g_vq);
    cudaGetSymbolAddress((void**)&p_sc, g_sc);   cudaGetSymbolAddress((void**)&p_h, g_h);
    cudaGetSymbolAddress((void**)&p_hn, g_hn);   cudaGetSymbolAddress((void**)&p_up1, g_up1);
    cudaGetSymbolAddress((void**)&p_moe, g_moe);
    cudaGetSymbolAddress((void**)&p_cnt, g_cnt); cudaGetSymbolAddress((void**)&p_tok, g_tok);
    cudaGetSymbolAddress((void**)&p_twt, g_twt);

    cudaFuncSetAttribute(gemm_tc<0>, cudaFuncAttributeMaxDynamicSharedMemorySize, SMEM_SZ);
    cudaFuncSetAttribute(gemm_tc<1>, cudaFuncAttributeMaxDynamicSharedMemorySize, SMEM_SZ);
    cudaFuncSetAttribute(gemm_tc<2>, cudaFuncAttributeMaxDynamicSharedMemorySize, SMEM_SZ);
    cudaFuncSetAttribute(gemm_tc<3>, cudaFuncAttributeMaxDynamicSharedMemorySize, SMEM_SZ);
    cudaFuncSetAttribute(gemm_tc<4>, cudaFuncAttributeMaxDynamicSharedMemorySize, SMEM_SZ);

    zero_kernel<<<8192, 256>>>(p_moe, p_cnt);

    quant_kernel<<<1024, 256>>>(w_q, p_wqh, p_wql, DD * DD / 128);
    quant_kernel<<<256, 256>>>(w_k, p_wkh, p_wkl, KV * HDIM * DD / 128);
    quant_kernel<<<256, 256>>>(w_v, p_wvh, p_wvl, KV * HDIM * DD / 128);
    quant_kernel<<<1024, 256>>>(w_o, p_woh, p_wol, DD * DD / 128);
    quant_kernel<<<28672, 256>>>(w1, p_w1h, p_w1l, EE * FFND * DD / 128);
    quant_kernel<<<28672, 256>>>(w3, p_w3h, p_w3l, EE * FFND * DD / 128);
    quant_kernel<<<28672, 256>>>(w2, p_w2h, p_w2l, EE * DD * FFND / 128);

    // ---- attention ----
    rms_split_kernel<false><<<TT, 256>>>(hidden, g1, nullptr, p_xnh, p_xnl);
    gemm_tc<0><<<dim3(8, 16, 1), 256, SMEM_SZ>>>(p_xnh, p_xnl, DD, 0, p_wqh, p_wql, DD, 0,
        p_qt, nullptr, nullptr, DD, 0, TT, nullptr, DD, nullptr, nullptr, nullptr);
    gemm_tc<0><<<dim3(2, 16, 1), 256, SMEM_SZ>>>(p_xnh, p_xnl, DD, 0, p_wkh, p_wkl, DD, 0,
        p_kt, nullptr, nullptr, KV * HDIM, 0, TT, nullptr, DD, nullptr, nullptr, nullptr);
    gemm_tc<0><<<dim3(2, 16, 1), 256, SMEM_SZ>>>(p_xnh, p_xnl, DD, 0, p_wvh, p_wvl, DD, 0,
        p_vt, nullptr, nullptr, KV * HDIM, 0, TT, nullptr, DD, nullptr, nullptr, nullptr);
    rope_q_kernel<<<TT * HH, HDIM>>>(p_qt, p_q);
    quant_row_kernel<true><<<TT * KV, HDIM>>>(p_kt, p_kr);
    quant_row_kernel<false><<<TT * KV, HDIM>>>(p_vt, p_vq);
    attn_scores_kernel<<<dim3(8, 8, BB * HH), 256>>>(p_q, p_kr, p_sc);
    softmax_kernel<<<BB * HH * SS, 256>>>(p_sc);
    attn_av_kernel<<<dim3(1, 8, BB * HH), 256>>>(p_sc, p_vq, p_oh, p_ol);
    gemm_tc<1><<<dim3(8, 16, 1), 256, SMEM_SZ>>>(p_oh, p_ol, DD, 0, p_woh, p_wol, DD, 0,
        p_h, nullptr, nullptr, DD, 0, TT, nullptr, DD, hidden, nullptr, nullptr);

    // ---- MoE ----
    rms_split_kernel<true><<<TT, 256>>>(p_h, g2, p_hn, p_hnh, p_hnl);
    router_kernel<<<TT, 256>>>(p_hn, w_gate);
    gemm_tc<2><<<dim3(28, 16, EE), 256, SMEM_SZ>>>(p_hnh, p_hnl, DD, 0,
        p_w1h, p_w1l, DD, (size_t)FFND * DD,
        p_up1, nullptr, nullptr, FFND, (size_t)TT * FFND,
        0, p_cnt, DD, nullptr, p_tok, nullptr);
    gemm_tc<4><<<dim3(28, 16, EE), 256, SMEM_SZ>>>(p_hnh, p_hnl, DD, 0,
        p_w3h, p_w3l, DD, (size_t)FFND * DD,
        nullptr, p_uph, p_upl, FFND, (size_t)TT * FFND,
        0, p_cnt, DD, p_up1, p_tok, nullptr);
    gemm_tc<3><<<dim3(8, 16, EE), 256, SMEM_SZ>>>(p_uph, p_upl, FFND, (size_t)TT * FFND,
        p_w2h, p_w2l, FFND, (size_t)DD * FFND,
        p_moe, nullptr, nullptr, DD, 0,
        0, p_cnt, FFND, nullptr, p_tok, p_twt);
    final_add_kernel<<<8192, 256>>>(p_h, p_moe, out);
}

// round 5
// speedup vs baseline: 2.9095x; 1.1804x over previous
#include <cuda_runtime.h>
#include <cuda_bf16.h>
#include <math.h>
#include <stdint.h>

#define BB 2
#define SS 1024
#define TT 2048
#define DD 1024
#define HH 8
#define KV 2
#define HDIM 128
#define EE 8
#define FFND 3584

#define KT 64
#define STAGES 3
#define TILE_BYTES 16384                 // 128 rows x 128 bytes
#define STAGE_BYTES (3 * TILE_BYTES)     // Ahi, Alo, Bn
#define SC_OFF (STAGES * STAGE_BYTES)    // 147456
#define SMEM_SZ (SC_OFF + 28 * 128 * 4)  // + scales (max 28 groups) = 161792

#define GBM 128
#define GBN 128
#define GBK 8

typedef __nv_bfloat16 bf16;

// weights: integer bf16 + per-group fp32 scale
__device__ bf16  g_wqn[DD * DD];           __device__ float g_wqs[DD * DD / 128];
__device__ bf16  g_wkn[KV * HDIM * DD];    __device__ float g_wks[KV * HDIM * DD / 128];
__device__ bf16  g_wvn[KV * HDIM * DD];    __device__ float g_wvs[KV * HDIM * DD / 128];
__device__ bf16  g_won[DD * DD];           __device__ float g_wos[DD * DD / 128];
__device__ bf16  g_w1n[EE * FFND * DD];    __device__ float g_w1s[EE * FFND * DD / 128];
__device__ bf16  g_w3n[EE * FFND * DD];    __device__ float g_w3s[EE * FFND * DD / 128];
__device__ bf16  g_w2n[EE * DD * FFND];    __device__ float g_w2s[EE * DD * FFND / 128];
// activations hi/lo
__device__ bf16 g_xnh[TT * DD];        __device__ bf16 g_xnl[TT * DD];
__device__ bf16 g_hnh[TT * DD];        __device__ bf16 g_hnl[TT * DD];
__device__ bf16 g_oh[TT * DD];         __device__ bf16 g_ol[TT * DD];
__device__ bf16 g_uph[EE * TT * FFND]; __device__ bf16 g_upl[EE * TT * FFND];
__device__ float g_qt[TT * DD];
__device__ float g_q[TT * DD];
__device__ float g_kt[TT * KV * HDIM];
__device__ float g_kr[TT * KV * HDIM];
__device__ float g_vt[TT * KV * HDIM];
__device__ float g_vq[TT * KV * HDIM];
__device__ float g_sc[BB * HH * SS * SS];
__device__ float g_h[TT * DD];
__device__ float g_hn[TT * DD];
__device__ float g_up1[EE * TT * FFND];
__device__ float g_moe[TT * DD];
__device__ int   g_cnt[EE];
__device__ int   g_tok[EE * TT];
__device__ float g_twt[EE * TT];

// ---------------- ptx helpers ----------------
__device__ __forceinline__ uint32_t smem_u32(const void* p) {
    uint32_t a;
    asm("{ .reg .u64 t; cvta.to.shared.u64 t, %1; cvt.u32.u64 %0, t; }" : "=r"(a) : "l"(p));
    return a;
}
__device__ __forceinline__ void ldsm4(uint32_t a, uint32_t& r0, uint32_t& r1,
                                      uint32_t& r2, uint32_t& r3) {
    asm volatile("ldmatrix.sync.aligned.m8n8.x4.shared.b16 {%0,%1,%2,%3}, [%4];"
                 : "=r"(r0), "=r"(r1), "=r"(r2), "=r"(r3) : "r"(a));
}
__device__ __forceinline__ void mma16816(float* c, const uint32_t* a, const uint32_t* b) {
    asm volatile("mma.sync.aligned.m16n8k16.row.col.f32.bf16.bf16.f32 "
                 "{%0,%1,%2,%3}, {%4,%5,%6,%7}, {%8,%9}, {%0,%1,%2,%3};"
                 : "+f"(c[0]), "+f"(c[1]), "+f"(c[2]), "+f"(c[3])
                 : "r"(a[0]), "r"(a[1]), "r"(a[2]), "r"(a[3]), "r"(b[0]), "r"(b[1]));
}
__device__ __forceinline__ void cpa16(uint32_t dst, const void* src) {
    asm volatile("cp.async.cg.shared.global [%0], [%1], 16;" :: "r"(dst), "l"(src));
}
__device__ __forceinline__ void cpa_commit() { asm volatile("cp.async.commit_group;" ::: "memory"); }
__device__ __forceinline__ void cpa_wait1() { asm volatile("cp.async.wait_group 1;" ::: "memory"); }

__device__ __forceinline__ float warp_min(float v) {
    #pragma unroll
    for (int o = 16; o; o >>= 1) v = fminf(v, __shfl_xor_sync(0xffffffffu, v, o));
    return v;
}
__device__ __forceinline__ float warp_max(float v) {
    #pragma unroll
    for (int o = 16; o; o >>= 1) v = fmaxf(v, __shfl_xor_sync(0xffffffffu, v, o));
    return v;
}
__device__ __forceinline__ float warp_sum(float v) {
    #pragma unroll
    for (int o = 16; o; o >>= 1) v += __shfl_xor_sync(0xffffffffu, v, o);
    return v;
}
__device__ __forceinline__ void split_bf(float v, bf16& h, bf16& l) {
    h = __float2bfloat16(v);
    l = __float2bfloat16(v - __bfloat162float(h));
}
__device__ __forceinline__ uint32_t swz(uint32_t off) { return off ^ ((off >> 3) & 0x70); }

// ---------------- small kernels ----------------
__global__ void zero_kernel(float* __restrict__ moe, int* __restrict__ cnt) {
    int i = blockIdx.x * 256 + threadIdx.x;
    if (i < TT * DD) moe[i] = 0.f;
    if (i < EE) cnt[i] = 0;
}

// weight quant: emit integer part n (bf16, exact) + per-group scale (fp32)
__global__ void quantw_kernel(const float* __restrict__ w, bf16* __restrict__ nq,
                              float* __restrict__ sc, int ngroups) {
    int g = blockIdx.x * 8 + (threadIdx.x >> 5);
    if (g >= ngroups) return;
    int lane = threadIdx.x & 31;
    float4 v = reinterpret_cast<const float4*>(w)[(size_t)g * 32 + lane];
    float mn = fminf(fminf(v.x, v.y), fminf(v.z, v.w));
    float mx = fmaxf(fmaxf(v.x, v.y), fmaxf(v.z, v.w));
    mn = warp_min(mn); mx = warp_max(mx);
    float scale = fmaxf(mx - mn, 1e-5f) / 15.0f;
    float base = fminf(fmaxf(rintf(-mn / scale), 0.f), 15.f);
    float r[4] = {v.x, v.y, v.z, v.w};
    bf16 n4[4];
    #pragma unroll
    for (int j = 0; j < 4; j++) {
        float q = fminf(fmaxf(rintf(r[j] / scale) + base, 0.f), 15.f) - base;
        n4[j] = __float2bfloat16(q);  // exact: integer in [-15,15]
    }
    size_t idx = (size_t)g * 128 + lane * 4;
    *reinterpret_cast<uint2*>(nq + idx) = *reinterpret_cast<uint2*>(n4);
    if (lane == 0) sc[g] = scale;
}

template<bool WF32>
__global__ void rms_split_kernel(const float* __restrict__ x, const float* __restrict__ g,
                                 float* __restrict__ f32o, bf16* __restrict__ hi,
                                 bf16* __restrict__ lo) {
    int row = blockIdx.x;
    const float* xr = x + (size_t)row * DD;
    float s = 0.f;
    for (int i = threadIdx.x; i < DD; i += 256) { float v = xr[i]; s += v * v; }
    __shared__ float sh[256];
    sh[threadIdx.x] = s; __syncthreads();
    for (int o2 = 128; o2; o2 >>= 1) {
        if (threadIdx.x < o2) sh[threadIdx.x] += sh[threadIdx.x + o2];
        __syncthreads();
    }
    float inv = rsqrtf(sh[0] * (1.0f / DD) + 1e-5f);
    for (int i = threadIdx.x; i < DD; i += 256) {
        float v = xr[i] * inv * g[i];
        if (WF32) f32o[(size_t)row * DD + i] = v;
        bf16 h, l; split_bf(v, h, l);
        hi[(size_t)row * DD + i] = h;
        lo[(size_t)row * DD + i] = l;
    }
}

// ===== bf16x2 mma.sync GEMM with exact integer weights + per-group rescale =====
// C = A @ (N*s)^T.  MODE 0 store f32 | 1 +resid | 2 gather-A, M=Mptr[z] |
// 3 scatter-add w/ wts | 4 gather-A, silu(resid)*acc split-> CH/CL
template<int MODE>
__global__ __launch_bounds__(256, 1) void gemm_tc(
    const bf16* __restrict__ Ahi, const bf16* __restrict__ Alo, int lda, size_t strideA,
    const bf16* __restrict__ Bn, const float* __restrict__ Bsc, int ldb,
    size_t strideB, size_t strideBs,
    float* __restrict__ C, bf16* __restrict__ CH, bf16* __restrict__ CL,
    int ldc, size_t strideC,
    int M, const int* __restrict__ Mptr, int K,
    const float* __restrict__ resid, const int* __restrict__ idx,
    const float* __restrict__ wts)
{
    int z = blockIdx.z;
    if (Mptr) M = Mptr[z];
    int m0 = blockIdx.y * 128;
    if (m0 >= M) return;
    int n0 = blockIdx.x * 128;
    int tid = threadIdx.x;
    int wid = tid >> 5, lid = tid & 31;

    extern __shared__ char smem[];
    uint32_t sb = smem_u32(smem);
    float* scs = reinterpret_cast<float*>(smem + SC_OFF);
    const int* idxz = (MODE >= 2) ? (idx + (size_t)z * TT) : (const int*)nullptr;
    int G = K >> 7;  // groups of 128

    // load per-column group scales into smem (before first __syncthreads of loop)
    for (int i = tid; i < G * 128; i += 256) {
        int g = i >> 7, c = i & 127;
        scs[i] = Bsc[strideBs * z + (size_t)(n0 + c) * G + g];
    }

    // per-thread cp.async slots: 3072 chunks of 16B / 256 thr = 12 each
    // slots 0-3: Ahi rows, 4-7: Alo (same rows, +dlo), 8-11: Bn
    const bf16* srcA[4]; const bf16* srcB[4];
    uint32_t dstA[4], dstB[4];
    ptrdiff_t dlo = Alo - Ahi;
    #pragma unroll
    for (int ci = 0; ci < 4; ci++) {
        int gid = ci * 256 + tid;
        int r = (gid >> 3) & 127;
        int c8 = gid & 7;
        int row = m0 + r;
        if (row >= M) row = m0;
        int rg = (MODE == 2 || MODE == 4) ? idxz[row] : row;
        srcA[ci] = Ahi + strideA * (size_t)z + (size_t)rg * lda + c8 * 8;
        dstA[ci] = swz((uint32_t)(r * 128 + c8 * 16));
        int gid2 = 2048 + gid;
        int r2 = (gid2 >> 3) & 127;
        int c82 = gid2 & 7;
        srcB[ci] = Bn + strideB * (size_t)z + (size_t)(n0 + r2) * ldb + c82 * 8;
        dstB[ci] = (uint32_t)(2 * TILE_BYTES) + swz((uint32_t)(r2 * 128 + c82 * 16));
    }

    int n_kt = K / KT;
    #pragma unroll 1
    for (int p = 0; p < STAGES - 1; p++) {
        uint32_t base = sb + p * STAGE_BYTES;
        size_t ko = (size_t)p * KT;
        #pragma unroll
        for (int ci = 0; ci < 4; ci++) {
            cpa16(base + dstA[ci], srcA[ci] + ko);
            cpa16(base + TILE_BYTES + dstA[ci], srcA[ci] + dlo + ko);
            cpa16(base + dstB[ci], srcB[ci] + ko);
        }
        cpa_commit();
    }

    int wr = (wid & 3) * 32;
    int wc = (wid >> 2) * 64;
    int rowm = (lid & 7) + ((lid >> 3) & 1) * 8;
    int colb = (lid >> 4) * 16;

    float acc[2][8][4] = {};
    float accg[2][8][4] = {};

    #pragma unroll 1
    for (int kt = 0; kt < n_kt; kt++) {
        cpa_wait1();
        __syncthreads();
        if (kt + STAGES - 1 < n_kt) {
            int sl = (kt + STAGES - 1) % STAGES;
            uint32_t base = sb + sl * STAGE_BYTES;
            size_t ko = (size_t)(kt + STAGES - 1) * KT;
            #pragma unroll
            for (int ci = 0; ci < 4; ci++) {
                cpa16(base + dstA[ci], srcA[ci] + ko);
                cpa16(base + TILE_BYTES + dstA[ci], srcA[ci] + dlo + ko);
                cpa16(base + dstB[ci], srcB[ci] + ko);
            }
            cpa_commit();
        }
        uint32_t sbase = sb + (kt % STAGES) * STAGE_BYTES;
        #pragma unroll
        for (int s16 = 0; s16 < 4; s16++) {
            int kb0 = s16 * 32 + colb;
            uint32_t ah[2][4], al[2][4], bn[8][2];
            #pragma unroll
            for (int i = 0; i < 2; i++) {
                uint32_t off = (uint32_t)((wr + i * 16 + rowm) * 128 + kb0);
                ldsm4(sbase + swz(off), ah[i][0], ah[i][1], ah[i][2], ah[i][3]);
                ldsm4(sbase + TILE_BYTES + swz(off), al[i][0], al[i][1], al[i][2], al[i][3]);
            }
            #pragma unroll
            for (int j = 0; j < 4; j++) {
                uint32_t off = (uint32_t)((wc + j * 16 + rowm) * 128 + kb0);
                uint32_t r0, r1, r2, r3;
                ldsm4(sbase + 2 * TILE_BYTES + swz(off), r0, r1, r2, r3);
                bn[j * 2][0] = r0; bn[j * 2][1] = r2;
                bn[j * 2 + 1][0] = r1; bn[j * 2 + 1][1] = r3;
            }
            #pragma unroll
            for (int i = 0; i < 2; i++)
                #pragma unroll
                for (int jn = 0; jn < 8; jn++) {
                    mma16816(accg[i][jn], ah[i], bn[jn]);
                    mma16816(accg[i][jn], al[i], bn[jn]);
                }
        }
        if (kt & 1) {  // end of a 128-k quant group: fold with scale
            int g = kt >> 1;
            #pragma unroll
            for (int jn = 0; jn < 8; jn++) {
                int c = wc + jn * 8 + (lid & 3) * 2;
                float s0 = scs[g * 128 + c];
                float s1 = scs[g * 128 + c + 1];
                #pragma unroll
                for (int i = 0; i < 2; i++) {
                    acc[i][jn][0] += s0 * accg[i][jn][0];
                    acc[i][jn][1] += s1 * accg[i][jn][1];
                    acc[i][jn][2] += s0 * accg[i][jn][2];
                    acc[i][jn][3] += s1 * accg[i][jn][3];
                    accg[i][jn][0] = 0.f; accg[i][jn][1] = 0.f;
                    accg[i][jn][2] = 0.f; accg[i][jn][3] = 0.f;
                }
            }
        }
    }

    // epilogue
    #pragma unroll
    for (int i = 0; i < 2; i++) {
        #pragma unroll
        for (int jn = 0; jn < 8; jn++) {
            int r0 = m0 + wr + i * 16 + (lid >> 2);
            int cc = n0 + wc + jn * 8 + (lid & 3) * 2;
            #pragma unroll
            for (int half = 0; half < 2; half++) {
                int row = r0 + half * 8;
                if (row >= M) continue;
                float v0 = acc[i][jn][half * 2 + 0];
                float v1 = acc[i][jn][half * 2 + 1];
                if (MODE == 0 || MODE == 1 || MODE == 2) {
                    float* Cr = C + strideC * z + (size_t)row * ldc + cc;
                    if (MODE == 1) {
                        const float* rr = resid + (size_t)row * ldc + cc;
                        v0 += rr[0]; v1 += rr[1];
                    }
                    *reinterpret_cast<float2*>(Cr) = make_float2(v0, v1);
                } else if (MODE == 3) {
                    int tk = idxz[row];
                    float w = wts[(size_t)z * TT + row];
                    float* Cr = C + (size_t)tk * ldc + cc;
                    atomicAdd(Cr + 0, w * v0);
                    atomicAdd(Cr + 1, w * v1);
                } else {  // MODE 4
                    const float* ar = resid + strideC * z + (size_t)row * ldc + cc;
                    float a0 = ar[0], a1 = ar[1];
                    float gv0 = (a0 / (1.f + expf(-a0))) * v0;
                    float gv1 = (a1 / (1.f + expf(-a1))) * v1;
                    bf16 h0, l0, h1, l1;
                    split_bf(gv0, h0, l0); split_bf(gv1, h1, l1);
                    size_t o = strideC * z + (size_t)row * ldc + cc;
                    CH[o] = h0; CH[o + 1] = h1;
                    CL[o] = l0; CL[o + 1] = l1;
                }
            }
        }
    }
}

// ---------------- RoPE / kv quant ----------------
__global__ void rope_q_kernel(const float* __restrict__ in, float* __restrict__ out) {
    int rowid = blockIdx.x;
    int d = threadIdx.x;
    __shared__ float sh[HDIM];
    sh[d] = in[(size_t)rowid * HDIM + d];
    __syncthreads();
    int pos = (rowid / HH) & (SS - 1);
    int i = d & 63;
    float invf = expf(-13.815510557964274f * ((float)(2 * i) * (1.0f / HDIM)));
    float f = (float)pos * invf;
    float c = cosf(f), sn = sinf(f);
    float v = (d < 64) ? (sh[d] * c - sh[d + 64] * sn)
                       : (sh[d] * c + sh[d - 64] * sn);
    out[(size_t)rowid * HDIM + d] = v;
}

template<bool DOROPE>
__global__ void quant_row_kernel(const float* __restrict__ in, float* __restrict__ out) {
    int rowid = blockIdx.x;
    int d = threadIdx.x;
    float v = in[(size_t)rowid * HDIM + d];
    __shared__ float smn[HDIM], smx[HDIM], sh[HDIM];
    smn[d] = v; smx[d] = v; __syncthreads();
    for (int o2 = 64; o2; o2 >>= 1) {
        if (d < o2) {
            smn[d] = fminf(smn[d], smn[d + o2]);
            smx[d] = fmaxf(smx[d], smx[d + o2]);
        }
        __syncthreads();
    }
    float scale = fmaxf(smx[0] - smn[0], 1e-5f) / 15.0f;
    float base = fminf(fmaxf(rintf(-smn[0] / scale), 0.f), 15.f);
    float q = (fminf(fmaxf(rintf(v / scale) + base, 0.f), 15.f) - base) * scale;
    if (DOROPE) {
        sh[d] = q; __syncthreads();
        int pos = (rowid / KV) & (SS - 1);
        int i = d & 63;
        float invf = expf(-13.815510557964274f * ((float)(2 * i) * (1.0f / HDIM)));
        float f = (float)pos * invf;
        float c = cosf(f), sn = sinf(f);
        q = (d < 64) ? (sh[d] * c - sh[d + 64] * sn)
                     : (sh[d] * c + sh[d - 64] * sn);
    }
    out[(size_t)rowid * HDIM + d] = q;
}

// ---------------- attention (SIMT fp32) ----------------
__global__ __launch_bounds__(256) void attn_scores_kernel(
    const float* __restrict__ q, const float* __restrict__ k, float* __restrict__ sc)
{
    int z = blockIdx.z;
    int m0 = blockIdx.y * GBM, n0 = blockIdx.x * GBN;
    if (n0 >= m0 + GBM) return;
    int b = z >> 3, h = z & 7;
    const float* A = q + ((size_t)b * SS * HH + h) * HDIM;
    const float* Bp = k + ((size_t)b * SS * KV + (h >> 2)) * HDIM;
    float* C = sc + (size_t)z * SS * SS;

    __shared__ float As[GBK][GBM], Bs[GBK][GBN];
    int t = threadIdx.x;
    int lrow = t >> 1, lk = (t & 1) * 4;
    int ty = t >> 4, tx = t & 15;
    const float* Arow = A + (size_t)(m0 + lrow) * (HH * HDIM);
    const float* Brow = Bp + (size_t)(n0 + lrow) * (KV * HDIM);
    float acc[8][8] = {};
    for (int k0 = 0; k0 < HDIM; k0 += GBK) {
        float4 av = *reinterpret_cast<const float4*>(Arow + k0 + lk);
        float4 bv = *reinterpret_cast<const float4*>(Brow + k0 + lk);
        As[lk + 0][lrow] = av.x; As[lk + 1][lrow] = av.y;
        As[lk + 2][lrow] = av.z; As[lk + 3][lrow] = av.w;
        Bs[lk + 0][lrow] = bv.x; Bs[lk + 1][lrow] = bv.y;
        Bs[lk + 2][lrow] = bv.z; Bs[lk + 3][lrow] = bv.w;
        __syncthreads();
        #pragma unroll
        for (int kk = 0; kk < GBK; kk++) {
            float a[8], bb[8];
            *reinterpret_cast<float4*>(&a[0]) = *reinterpret_cast<const float4*>(&As[kk][ty * 8]);
            *reinterpret_cast<float4*>(&a[4]) = *reinterpret_cast<const float4*>(&As[kk][ty * 8 + 4]);
            *reinterpret_cast<float4*>(&bb[0]) = *reinterpret_cast<const float4*>(&Bs[kk][tx * 8]);
            *reinterpret_cast<float4*>(&bb[4]) = *reinterpret_cast<const float4*>(&Bs[kk][tx * 8 + 4]);
            #pragma unroll
            for (int i = 0; i < 8; i++)
                #pragma unroll
                for (int j = 0; j < 8; j++)
                    acc[i][j] += a[i] * bb[j];
        }
        __syncthreads();
    }
    const float scalef = 0.08838834764831845f;
    #pragma unroll
    for (int i = 0; i < 8; i++) {
        int row = m0 + ty * 8 + i;
        float* Cr = C + (size_t)row * SS + n0 + tx * 8;
        #pragma unroll
        for (int j = 0; j < 8; j++) Cr[j] = acc[i][j] * scalef;
    }
}

__global__ void softmax_kernel(float* __restrict__ sc) {
    int r = blockIdx.x;
    int s = r & (SS - 1);
    float* row = sc + (size_t)r * SS;
    int n = s + 1;
    __shared__ float sh[256];
    float m = -INFINITY;
    for (int i = threadIdx.x; i < n; i += 256) m = fmaxf(m, row[i]);
    sh[threadIdx.x] = m; __syncthreads();
    for (int o2 = 128; o2; o2 >>= 1) {
        if (threadIdx.x < o2) sh[threadIdx.x] = fmaxf(sh[threadIdx.x], sh[threadIdx.x + o2]);
        __syncthreads();
    }
    m = sh[0]; __syncthreads();
    float sum = 0.f;
    for (int i = threadIdx.x; i < n; i += 256) {
        float e = expf(row[i] - m);
        row[i] = e; sum += e;
    }
    sh[threadIdx.x] = sum; __syncthreads();
    for (int o2 = 128; o2; o2 >>= 1) {
        if (threadIdx.x < o2) sh[threadIdx.x] += sh[threadIdx.x + o2];
        __syncthreads();
    }
    float inv = 1.0f / sh[0];
    for (int i = threadIdx.x; i < SS; i += 256)
        row[i] = (i < n) ? row[i] * inv : 0.f;
}

__global__ __launch_bounds__(256) void attn_av_kernel(
    const float* __restrict__ p, const float* __restrict__ v,
    bf16* __restrict__ oh, bf16* __restrict__ ol)
{
    int z = blockIdx.z;
    int b = z >> 3, h = z & 7;
    int m0 = blockIdx.y * GBM;
    const float* A = p + (size_t)z * SS * SS;
    const float* V = v + ((size_t)b * SS * KV + (h >> 2)) * HDIM;

    __shared__ float As[GBK][GBM], Bs[GBK][GBN];
    int t = threadIdx.x;
    int lrow = t >> 1, lk = (t & 1) * 4;
    int bk = t >> 5, bn = (t & 31) * 4;
    int ty = t >> 4, tx = t & 15;
    float acc[8][8] = {};
    int kend = m0 + GBM;
    for (int k0 = 0; k0 < kend; k0 += GBK) {
        float4 av = *reinterpret_cast<const float4*>(A + (size_t)(m0 + lrow) * SS + k0 + lk);
        As[lk + 0][lrow] = av.x; As[lk + 1][lrow] = av.y;
        As[lk + 2][lrow] = av.z; As[lk + 3][lrow] = av.w;
        float4 bv = *reinterpret_cast<const float4*>(V + (size_t)(k0 + bk) * (KV * HDIM) + bn);
        *reinterpret_cast<float4*>(&Bs[bk][bn]) = bv;
        __syncthreads();
        #pragma unroll
        for (int kk = 0; kk < GBK; kk++) {
            float a[8], bb[8];
            *reinterpret_cast<float4*>(&a[0]) = *reinterpret_cast<const float4*>(&As[kk][ty * 8]);
            *reinterpret_cast<float4*>(&a[4]) = *reinterpret_cast<const float4*>(&As[kk][ty * 8 + 4]);
            *reinterpret_cast<float4*>(&bb[0]) = *reinterpret_cast<const float4*>(&Bs[kk][tx * 8]);
            *reinterpret_cast<float4*>(&bb[4]) = *reinterpret_cast<const float4*>(&Bs[kk][tx * 8 + 4]);
            #pragma unroll
            for (int i = 0; i < 8; i++)
                #pragma unroll
                for (int j = 0; j < 8; j++)
                    acc[i][j] += a[i] * bb[j];
        }
        __syncthreads();
    }
    #pragma unroll
    for (int i = 0; i < 8; i++) {
        int row = m0 + ty * 8 + i;
        size_t base = ((size_t)(b * SS + row) * HH + h) * HDIM + tx * 8;
        #pragma unroll
        for (int j = 0; j < 8; j++) {
            bf16 hv, lv; split_bf(acc[i][j], hv, lv);
            oh[base + j] = hv; ol[base + j] = lv;
        }
    }
}

// ---------------- router ----------------
__global__ __launch_bounds__(256) void router_kernel(
    const float* __restrict__ hn, const float* __restrict__ wg)
{
    int tkn = blockIdx.x;
    int w = threadIdx.x >> 5, lane = threadIdx.x & 31;
    const float* x = hn + (size_t)tkn * DD;
    const float* g = wg + (size_t)w * DD;
    float s = 0.f;
    for (int i = lane; i < DD; i += 32) s += x[i] * g[i];
    s = warp_sum(s);
    __shared__ float lg[EE];
    if (lane == 0) lg[w] = s;
    __syncthreads();
    if (threadIdx.x == 0) {
        float m = -INFINITY;
        #pragma unroll
        for (int e = 0; e < EE; e++) m = fmaxf(m, lg[e]);
        float ex[EE];
        #pragma unroll
        for (int e = 0; e < EE; e++) ex[e] = expf(lg[e] - m);
        int i1 = 0; float m1 = ex[0];
        #pragma unroll
        for (int e = 1; e < EE; e++) if (ex[e] > m1) { m1 = ex[e]; i1 = e; }
        int i2 = -1; float m2 = -1.f;
        #pragma unroll
        for (int e = 0; e < EE; e++) if (e != i1 && ex[e] > m2) { m2 = ex[e]; i2 = e; }
        float inv = 1.0f / (m1 + m2);
        int p1 = atomicAdd(&g_cnt[i1], 1);
        g_tok[i1 * TT + p1] = tkn; g_twt[i1 * TT + p1] = m1 * inv;
        int p2 = atomicAdd(&g_cnt[i2], 1);
        g_tok[i2 * TT + p2] = tkn; g_twt[i2 * TT + p2] = m2 * inv;
    }
}

__global__ void final_add_kernel(const float* __restrict__ h, const float* __restrict__ moe,
                                 float* __restrict__ out) {
    int i = blockIdx.x * 256 + threadIdx.x;
    out[i] = h[i] + moe[i];
}

// ======================= host =======================
extern "C" void kernel_launch(void* const* d_in, const int* in_sizes, int n_in,
                              void* d_out, int out_size) {
    const float* hidden = (const float*)d_in[0];
    const float* w_q    = (const float*)d_in[1];
    const float* w_k    = (const float*)d_in[2];
    const float* w_v    = (const float*)d_in[3];
    const float* w_o    = (const float*)d_in[4];
    const float* g1     = (const float*)d_in[5];
    const float* g2     = (const float*)d_in[6];
    const float* w_gate = (const float*)d_in[7];
    const float* w1     = (const float*)d_in[8];
    const float* w3     = (const float*)d_in[9];
    const float* w2     = (const float*)d_in[10];
    float* out = (float*)d_out;

    bf16 *p_wqn, *p_wkn, *p_wvn, *p_won, *p_w1n, *p_w3n, *p_w2n;
    float *p_wqs, *p_wks, *p_wvs, *p_wos, *p_w1s, *p_w3s, *p_w2s;
    bf16 *p_xnh, *p_xnl, *p_hnh, *p_hnl, *p_oh, *p_ol, *p_uph, *p_upl;
    float *p_qt, *p_q, *p_kt, *p_kr, *p_vt, *p_vq, *p_sc, *p_h, *p_hn, *p_up1, *p_moe, *p_twt;
    int *p_cnt, *p_tok;
    cudaGetSymbolAddress((void**)&p_wqn, g_wqn); cudaGetSymbolAddress((void**)&p_wqs, g_wqs);
    cudaGetSymbolAddress((void**)&p_wkn, g_wkn); cudaGetSymbolAddress((void**)&p_wks, g_wks);
    cudaGetSymbolAddress((void**)&p_wvn, g_wvn); cudaGetSymbolAddress((void**)&p_wvs, g_wvs);
    cudaGetSymbolAddress((void**)&p_won, g_won); cudaGetSymbolAddress((void**)&p_wos, g_wos);
    cudaGetSymbolAddress((void**)&p_w1n, g_w1n); cudaGetSymbolAddress((void**)&p_w1s, g_w1s);
    cudaGetSymbolAddress((void**)&p_w3n, g_w3n); cudaGetSymbolAddress((void**)&p_w3s, g_w3s);
    cudaGetSymbolAddress((void**)&p_w2n, g_w2n); cudaGetSymbolAddress((void**)&p_w2s, g_w2s);
    cudaGetSymbolAddress((void**)&p_xnh, g_xnh); cudaGetSymbolAddress((void**)&p_xnl, g_xnl);
    cudaGetSymbolAddress((void**)&p_hnh, g_hnh); cudaGetSymbolAddress((void**)&p_hnl, g_hnl);
    cudaGetSymbolAddress((void**)&p_oh, g_oh);   cudaGetSymbolAddress((void**)&p_ol, g_ol);
    cudaGetSymbolAddress((void**)&p_uph, g_uph); cudaGetSymbolAddress((void**)&p_upl, g_upl);
    cudaGetSymbolAddress((void**)&p_qt, g_qt);   cudaGetSymbolAddress((void**)&p_q, g_q);
    cudaGetSymbolAddress((void**)&p_kt, g_kt);   cudaGetSymbolAddress((void**)&p_kr, g_kr);
    cudaGetSymbolAddress((void**)&p_vt, g_vt);   cudaGetSymbolAddress((void**)&p_vq, g_vq);
    cudaGetSymbolAddress((void**)&p_sc, g_sc);   cudaGetSymbolAddress((void**)&p_h, g_h);
    cudaGetSymbolAddress((void**)&p_hn, g_hn);   cudaGetSymbolAddress((void**)&p_up1, g_up1);
    cudaGetSymbolAddress((void**)&p_moe, g_moe);
    cudaGetSymbolAddress((void**)&p_cnt, g_cnt); cudaGetSymbolAddress((void**)&p_tok, g_tok);
    cudaGetSymbolAddress((void**)&p_twt, g_twt);

    cudaFuncSetAttribute(gemm_tc<0>, cudaFuncAttributeMaxDynamicSharedMemorySize, SMEM_SZ);
    cudaFuncSetAttribute(gemm_tc<1>, cudaFuncAttributeMaxDynamicSharedMemorySize, SMEM_SZ);
    cudaFuncSetAttribute(gemm_tc<2>, cudaFuncAttributeMaxDynamicSharedMemorySize, SMEM_SZ);
    cudaFuncSetAttribute(gemm_tc<3>, cudaFuncAttributeMaxDynamicSharedMemorySize, SMEM_SZ);
    cudaFuncSetAttribute(gemm_tc<4>, cudaFuncAttributeMaxDynamicSharedMemorySize, SMEM_SZ);

    zero_kernel<<<8192, 256>>>(p_moe, p_cnt);

    quantw_kernel<<<1024, 256>>>(w_q, p_wqn, p_wqs, DD * DD / 128);
    quantw_kernel<<<256, 256>>>(w_k, p_wkn, p_wks, KV * HDIM * DD / 128);
    quantw_kernel<<<256, 256>>>(w_v, p_wvn, p_wvs, KV * HDIM * DD / 128);
    quantw_kernel<<<1024, 256>>>(w_o, p_won, p_wos, DD * DD / 128);
    quantw_kernel<<<28672, 256>>>(w1, p_w1n, p_w1s, EE * FFND * DD / 128);
    quantw_kernel<<<28672, 256>>>(w3, p_w3n, p_w3s, EE * FFND * DD / 128);
    quantw_kernel<<<28672, 256>>>(w2, p_w2n, p_w2s, EE * DD * FFND / 128);

    // ---- attention ----
    rms_split_kernel<false><<<TT, 256>>>(hidden, g1, nullptr, p_xnh, p_xnl);
    gemm_tc<0><<<dim3(8, 16, 1), 256, SMEM_SZ>>>(p_xnh, p_xnl, DD, 0,
        p_wqn, p_wqs, DD, 0, 0,
        p_qt, nullptr, nullptr, DD, 0, TT, nullptr, DD, nullptr, nullptr, nullptr);
    gemm_tc<0><<<dim3(2, 16, 1), 256, SMEM_SZ>>>(p_xnh, p_xnl, DD, 0,
        p_wkn, p_wks, DD, 0, 0,
        p_kt, nullptr, nullptr, KV * HDIM, 0, TT, nullptr, DD, nullptr, nullptr, nullptr);
    gemm_tc<0><<<dim3(2, 16, 1), 256, SMEM_SZ>>>(p_xnh, p_xnl, DD, 0,
        p_wvn, p_wvs, DD, 0, 0,
        p_vt, nullptr, nullptr, KV * HDIM, 0, TT, nullptr, DD, nullptr, nullptr, nullptr);
    rope_q_kernel<<<TT * HH, HDIM>>>(p_qt, p_q);
    quant_row_kernel<true><<<TT * KV, HDIM>>>(p_kt, p_kr);
    quant_row_kernel<false><<<TT * KV, HDIM>>>(p_vt, p_vq);
    attn_scores_kernel<<<dim3(8, 8, BB * HH), 256>>>(p_q, p_kr, p_sc);
    softmax_kernel<<<BB * HH * SS, 256>>>(p_sc);
    attn_av_kernel<<<dim3(1, 8, BB * HH), 256>>>(p_sc, p_vq, p_oh, p_ol);
    gemm_tc<1><<<dim3(8, 16, 1), 256, SMEM_SZ>>>(p_oh, p_ol, DD, 0,
        p_won, p_wos, DD, 0, 0,
        p_h, nullptr, nullptr, DD, 0, TT, nullptr, DD, hidden, nullptr, nullptr);

    // ---- MoE ----
    rms_split_kernel<true><<<TT, 256>>>(p_h, g2, p_hn, p_hnh, p_hnl);
    router_kernel<<<TT, 256>>>(p_hn, w_gate);
    gemm_tc<2><<<dim3(28, 16, EE), 256, SMEM_SZ>>>(p_hnh, p_hnl, DD, 0,
        p_w1n, p_w1s, DD, (size_t)FFND * DD, (size_t)FFND * (DD / 128),
        p_up1, nullptr, nullptr, FFND, (size_t)TT * FFND,
        0, p_cnt, DD, nullptr, p_tok, nullptr);
    gemm_tc<4><<<dim3(28, 16, EE), 256, SMEM_SZ>>>(p_hnh, p_hnl, DD, 0,
        p_w3n, p_w3s, DD, (size_t)FFND * DD, (size_t)FFND * (DD / 128),
        nullptr, p_uph, p_upl, FFND, (size_t)TT * FFND,
        0, p_cnt, DD, p_up1, p_tok, nullptr);
    gemm_tc<3><<<dim3(8, 16, EE), 256, SMEM_SZ>>>(p_uph, p_upl, FFND, (size_t)TT * FFND,
        p_w2n, p_w2s, FFND, (size_t)DD * FFND, (size_t)DD * (FFND / 128),
        p_moe, nullptr, nullptr, DD, 0,
        0, p_cnt, FFND, nullptr, p_tok, p_twt);
    final_add_kernel<<<8192, 256>>>(p_h, p_moe, out);
}

// round 6
// speedup vs baseline: 3.4854x; 1.1980x over previous
#include <cuda_runtime.h>
#include <cuda_bf16.h>
#include <math.h>
#include <stdint.h>

#define BB 2
#define SS 1024
#define TT 2048
#define DD 1024
#define HH 8
#define KV 2
#define HDIM 128
#define EE 8
#define FFND 3584
#define NQKV 1536

#define KT 64
#define STAGES 3
#define TILE_BYTES 16384
#define STAGE_BYTES (3 * TILE_BYTES)
#define SC_OFF (STAGES * STAGE_BYTES)
#define SMEM_SZ (SC_OFF + 28 * 128 * 4)
// scores: 2 stages x 4 tiles x 16KB
#define SCR_SMEM (2 * 4 * TILE_BYTES)
// av: 3 stages x (Ph 16K + Pl 16K + V 16K)
#define AV_STAGE (3 * TILE_BYTES)
#define AV_SMEM (3 * AV_STAGE)

typedef __nv_bfloat16 bf16;

// weights: integer bf16 + per-group fp32 scale
__device__ bf16  g_wqkvn[NQKV * DD];       __device__ float g_wqkvs[NQKV * DD / 128];
__device__ bf16  g_won[DD * DD];           __device__ float g_wos[DD * DD / 128];
__device__ bf16  g_w1n[EE * FFND * DD];    __device__ float g_w1s[EE * FFND * DD / 128];
__device__ bf16  g_w3n[EE * FFND * DD];    __device__ float g_w3s[EE * FFND * DD / 128];
__device__ bf16  g_w2n[EE * DD * FFND];    __device__ float g_w2s[EE * DD * FFND / 128];
// activations
__device__ bf16 g_xnh[TT * DD];        __device__ bf16 g_xnl[TT * DD];
__device__ bf16 g_hnh[TT * DD];        __device__ bf16 g_hnl[TT * DD];
__device__ bf16 g_oh[TT * DD];         __device__ bf16 g_ol[TT * DD];
__device__ bf16 g_uph[EE * TT * FFND]; __device__ bf16 g_upl[EE * TT * FFND];
__device__ float g_qkv[TT * NQKV];
__device__ bf16 g_qh[TT * DD];         __device__ bf16 g_ql[TT * DD];
__device__ bf16 g_kh[TT * KV * HDIM];  __device__ bf16 g_kl[TT * KV * HDIM];
__device__ bf16 g_vn[TT * KV * HDIM];  __device__ float g_vs[TT * KV];
__device__ float g_sc[BB * HH * SS * SS];
__device__ bf16 g_ph[BB * HH * SS * SS];
__device__ bf16 g_pl[BB * HH * SS * SS];
__device__ float g_h[TT * DD];
__device__ float g_hn[TT * DD];
__device__ float g_up1[EE * TT * FFND];
__device__ float g_moe[TT * DD];
__device__ int   g_cnt[EE];
__device__ int   g_tok[EE * TT];
__device__ float g_twt[EE * TT];

// ---------------- ptx helpers ----------------
__device__ __forceinline__ uint32_t smem_u32(const void* p) {
    uint32_t a;
    asm("{ .reg .u64 t; cvta.to.shared.u64 t, %1; cvt.u32.u64 %0, t; }" : "=r"(a) : "l"(p));
    return a;
}
__device__ __forceinline__ void ldsm4(uint32_t a, uint32_t& r0, uint32_t& r1,
                                      uint32_t& r2, uint32_t& r3) {
    asm volatile("ldmatrix.sync.aligned.m8n8.x4.shared.b16 {%0,%1,%2,%3}, [%4];"
                 : "=r"(r0), "=r"(r1), "=r"(r2), "=r"(r3) : "r"(a));
}
__device__ __forceinline__ void ldsm4t(uint32_t a, uint32_t& r0, uint32_t& r1,
                                       uint32_t& r2, uint32_t& r3) {
    asm volatile("ldmatrix.sync.aligned.m8n8.x4.trans.shared.b16 {%0,%1,%2,%3}, [%4];"
                 : "=r"(r0), "=r"(r1), "=r"(r2), "=r"(r3) : "r"(a));
}
__device__ __forceinline__ void mma16816(float* c, const uint32_t* a, const uint32_t* b) {
    asm volatile("mma.sync.aligned.m16n8k16.row.col.f32.bf16.bf16.f32 "
                 "{%0,%1,%2,%3}, {%4,%5,%6,%7}, {%8,%9}, {%0,%1,%2,%3};"
                 : "+f"(c[0]), "+f"(c[1]), "+f"(c[2]), "+f"(c[3])
                 : "r"(a[0]), "r"(a[1]), "r"(a[2]), "r"(a[3]), "r"(b[0]), "r"(b[1]));
}
__device__ __forceinline__ void cpa16(uint32_t dst, const void* src) {
    asm volatile("cp.async.cg.shared.global [%0], [%1], 16;" :: "r"(dst), "l"(src));
}
__device__ __forceinline__ void cpa_commit() { asm volatile("cp.async.commit_group;" ::: "memory"); }
__device__ __forceinline__ void cpa_wait1() { asm volatile("cp.async.wait_group 1;" ::: "memory"); }
__device__ __forceinline__ void cpa_wait0() { asm volatile("cp.async.wait_group 0;" ::: "memory"); }

__device__ __forceinline__ float warp_min(float v) {
    #pragma unroll
    for (int o = 16; o; o >>= 1) v = fminf(v, __shfl_xor_sync(0xffffffffu, v, o));
    return v;
}
__device__ __forceinline__ float warp_max(float v) {
    #pragma unroll
    for (int o = 16; o; o >>= 1) v = fmaxf(v, __shfl_xor_sync(0xffffffffu, v, o));
    return v;
}
__device__ __forceinline__ float warp_sum(float v) {
    #pragma unroll
    for (int o = 16; o; o >>= 1) v += __shfl_xor_sync(0xffffffffu, v, o);
    return v;
}
__device__ __forceinline__ void split_bf(float v, bf16& h, bf16& l) {
    h = __float2bfloat16(v);
    l = __float2bfloat16(v - __bfloat162float(h));
}
__device__ __forceinline__ uint32_t swz(uint32_t off) { return off ^ ((off >> 3) & 0x70); }

// ---------------- small kernels ----------------
__global__ void zero_kernel(float* __restrict__ moe, int* __restrict__ cnt) {
    int i = blockIdx.x * 256 + threadIdx.x;
    if (i < TT * DD) moe[i] = 0.f;
    if (i < EE) cnt[i] = 0;
}

__global__ void quantw_kernel(const float* __restrict__ w, bf16* __restrict__ nq,
                              float* __restrict__ sc, int ngroups) {
    int g = blockIdx.x * 8 + (threadIdx.x >> 5);
    if (g >= ngroups) return;
    int lane = threadIdx.x & 31;
    float4 v = reinterpret_cast<const float4*>(w)[(size_t)g * 32 + lane];
    float mn = fminf(fminf(v.x, v.y), fminf(v.z, v.w));
    float mx = fmaxf(fmaxf(v.x, v.y), fmaxf(v.z, v.w));
    mn = warp_min(mn); mx = warp_max(mx);
    float scale = fmaxf(mx - mn, 1e-5f) / 15.0f;
    float base = fminf(fmaxf(rintf(-mn / scale), 0.f), 15.f);
    float r[4] = {v.x, v.y, v.z, v.w};
    bf16 n4[4];
    #pragma unroll
    for (int j = 0; j < 4; j++) {
        float q = fminf(fmaxf(rintf(r[j] / scale) + base, 0.f), 15.f) - base;
        n4[j] = __float2bfloat16(q);
    }
    size_t idx = (size_t)g * 128 + lane * 4;
    *reinterpret_cast<uint2*>(nq + idx) = *reinterpret_cast<uint2*>(n4);
    if (lane == 0) sc[g] = scale;
}

template<bool WF32>
__global__ void rms_split_kernel(const float* __restrict__ x, const float* __restrict__ g,
                                 float* __restrict__ f32o, bf16* __restrict__ hi,
                                 bf16* __restrict__ lo) {
    int row = blockIdx.x;
    const float* xr = x + (size_t)row * DD;
    float s = 0.f;
    for (int i = threadIdx.x; i < DD; i += 256) { float v = xr[i]; s += v * v; }
    __shared__ float sh[256];
    sh[threadIdx.x] = s; __syncthreads();
    for (int o2 = 128; o2; o2 >>= 1) {
        if (threadIdx.x < o2) sh[threadIdx.x] += sh[threadIdx.x + o2];
        __syncthreads();
    }
    float inv = rsqrtf(sh[0] * (1.0f / DD) + 1e-5f);
    for (int i = threadIdx.x; i < DD; i += 256) {
        float v = xr[i] * inv * g[i];
        if (WF32) f32o[(size_t)row * DD + i] = v;
        bf16 h, l; split_bf(v, h, l);
        hi[(size_t)row * DD + i] = h;
        lo[(size_t)row * DD + i] = l;
    }
}

// ===== bf16x2 mma.sync GEMM with exact integer weights + per-group rescale =====
template<int MODE>
__global__ __launch_bounds__(256, 1) void gemm_tc(
    const bf16* __restrict__ Ahi, const bf16* __restrict__ Alo, int lda, size_t strideA,
    const bf16* __restrict__ Bn, const float* __restrict__ Bsc, int ldb,
    size_t strideB, size_t strideBs,
    float* __restrict__ C, bf16* __restrict__ CH, bf16* __restrict__ CL,
    int ldc, size_t strideC,
    int M, const int* __restrict__ Mptr, int K,
    const float* __restrict__ resid, const int* __restrict__ idx,
    const float* __restrict__ wts)
{
    int z = blockIdx.z;
    if (Mptr) M = Mptr[z];
    int m0 = blockIdx.y * 128;
    if (m0 >= M) return;
    int n0 = blockIdx.x * 128;
    int tid = threadIdx.x;
    int wid = tid >> 5, lid = tid & 31;

    extern __shared__ char smem[];
    uint32_t sb = smem_u32(smem);
    float* scs = reinterpret_cast<float*>(smem + SC_OFF);
    const int* idxz = (MODE >= 2) ? (idx + (size_t)z * TT) : (const int*)nullptr;
    int G = K >> 7;

    for (int i = tid; i < G * 128; i += 256) {
        int g = i >> 7, c = i & 127;
        scs[i] = Bsc[strideBs * z + (size_t)(n0 + c) * G + g];
    }

    const bf16* srcA[4]; const bf16* srcB[4];
    uint32_t dstA[4], dstB[4];
    ptrdiff_t dlo = Alo - Ahi;
    #pragma unroll
    for (int ci = 0; ci < 4; ci++) {
        int gid = ci * 256 + tid;
        int r = (gid >> 3) & 127;
        int c8 = gid & 7;
        int row = m0 + r;
        if (row >= M) row = m0;
        int rg = (MODE == 2 || MODE == 4) ? idxz[row] : row;
        srcA[ci] = Ahi + strideA * (size_t)z + (size_t)rg * lda + c8 * 8;
        dstA[ci] = swz((uint32_t)(r * 128 + c8 * 16));
        int gid2 = 2048 + gid;
        int r2 = (gid2 >> 3) & 127;
        int c82 = gid2 & 7;
        srcB[ci] = Bn + strideB * (size_t)z + (size_t)(n0 + r2) * ldb + c82 * 8;
        dstB[ci] = (uint32_t)(2 * TILE_BYTES) + swz((uint32_t)(r2 * 128 + c82 * 16));
    }

    int n_kt = K / KT;
    #pragma unroll 1
    for (int p = 0; p < STAGES - 1; p++) {
        uint32_t base = sb + p * STAGE_BYTES;
        size_t ko = (size_t)p * KT;
        #pragma unroll
        for (int ci = 0; ci < 4; ci++) {
            cpa16(base + dstA[ci], srcA[ci] + ko);
            cpa16(base + TILE_BYTES + dstA[ci], srcA[ci] + dlo + ko);
            cpa16(base + dstB[ci], srcB[ci] + ko);
        }
        cpa_commit();
    }

    int wr = (wid & 3) * 32;
    int wc = (wid >> 2) * 64;
    int rowm = (lid & 7) + ((lid >> 3) & 1) * 8;
    int colb = (lid >> 4) * 16;

    float acc[2][8][4] = {};
    float accg[2][8][4] = {};

    #pragma unroll 1
    for (int kt = 0; kt < n_kt; kt++) {
        cpa_wait1();
        __syncthreads();
        if (kt + STAGES - 1 < n_kt) {
            int sl = (kt + STAGES - 1) % STAGES;
            uint32_t base = sb + sl * STAGE_BYTES;
            size_t ko = (size_t)(kt + STAGES - 1) * KT;
            #pragma unroll
            for (int ci = 0; ci < 4; ci++) {
                cpa16(base + dstA[ci], srcA[ci] + ko);
                cpa16(base + TILE_BYTES + dstA[ci], srcA[ci] + dlo + ko);
                cpa16(base + dstB[ci], srcB[ci] + ko);
            }
            cpa_commit();
        }
        uint32_t sbase = sb + (kt % STAGES) * STAGE_BYTES;
        #pragma unroll
        for (int s16 = 0; s16 < 4; s16++) {
            int kb0 = s16 * 32 + colb;
            uint32_t ah[2][4], al[2][4], bn[8][2];
            #pragma unroll
            for (int i = 0; i < 2; i++) {
                uint32_t off = (uint32_t)((wr + i * 16 + rowm) * 128 + kb0);
                ldsm4(sbase + swz(off), ah[i][0], ah[i][1], ah[i][2], ah[i][3]);
                ldsm4(sbase + TILE_BYTES + swz(off), al[i][0], al[i][1], al[i][2], al[i][3]);
            }
            #pragma unroll
            for (int j = 0; j < 4; j++) {
                uint32_t off = (uint32_t)((wc + j * 16 + rowm) * 128 + kb0);
                uint32_t r0, r1, r2, r3;
                ldsm4(sbase + 2 * TILE_BYTES + swz(off), r0, r1, r2, r3);
                bn[j * 2][0] = r0; bn[j * 2][1] = r2;
                bn[j * 2 + 1][0] = r1; bn[j * 2 + 1][1] = r3;
            }
            #pragma unroll
            for (int i = 0; i < 2; i++)
                #pragma unroll
                for (int jn = 0; jn < 8; jn++) {
                    mma16816(accg[i][jn], ah[i], bn[jn]);
                    mma16816(accg[i][jn], al[i], bn[jn]);
                }
        }
        if (kt & 1) {
            int g = kt >> 1;
            #pragma unroll
            for (int jn = 0; jn < 8; jn++) {
                int c = wc + jn * 8 + (lid & 3) * 2;
                float s0 = scs[g * 128 + c];
                float s1 = scs[g * 128 + c + 1];
                #pragma unroll
                for (int i = 0; i < 2; i++) {
                    acc[i][jn][0] += s0 * accg[i][jn][0];
                    acc[i][jn][1] += s1 * accg[i][jn][1];
                    acc[i][jn][2] += s0 * accg[i][jn][2];
                    acc[i][jn][3] += s1 * accg[i][jn][3];
                    accg[i][jn][0] = 0.f; accg[i][jn][1] = 0.f;
                    accg[i][jn][2] = 0.f; accg[i][jn][3] = 0.f;
                }
            }
        }
    }

    #pragma unroll
    for (int i = 0; i < 2; i++) {
        #pragma unroll
        for (int jn = 0; jn < 8; jn++) {
            int r0 = m0 + wr + i * 16 + (lid >> 2);
            int cc = n0 + wc + jn * 8 + (lid & 3) * 2;
            #pragma unroll
            for (int half = 0; half < 2; half++) {
                int row = r0 + half * 8;
                if (row >= M) continue;
                float v0 = acc[i][jn][half * 2 + 0];
                float v1 = acc[i][jn][half * 2 + 1];
                if (MODE == 0 || MODE == 1 || MODE == 2) {
                    float* Cr = C + strideC * z + (size_t)row * ldc + cc;
                    if (MODE == 1) {
                        const float* rr = resid + (size_t)row * ldc + cc;
                        v0 += rr[0]; v1 += rr[1];
                    }
                    *reinterpret_cast<float2*>(Cr) = make_float2(v0, v1);
                } else if (MODE == 3) {
                    int tk = idxz[row];
                    float w = wts[(size_t)z * TT + row];
                    float* Cr = C + (size_t)tk * ldc + cc;
                    atomicAdd(Cr + 0, w * v0);
                    atomicAdd(Cr + 1, w * v1);
                } else {
                    const float* ar = resid + strideC * z + (size_t)row * ldc + cc;
                    float a0 = ar[0], a1 = ar[1];
                    float gv0 = (a0 / (1.f + expf(-a0))) * v0;
                    float gv1 = (a1 / (1.f + expf(-a1))) * v1;
                    bf16 h0, l0, h1, l1;
                    split_bf(gv0, h0, l0); split_bf(gv1, h1, l1);
                    size_t o = strideC * z + (size_t)row * ldc + cc;
                    CH[o] = h0; CH[o + 1] = h1;
                    CL[o] = l0; CL[o + 1] = l1;
                }
            }
        }
    }
}

// ---------------- RoPE (q -> bf16 hi/lo) ----------------
__global__ void rope_q_kernel(const float* __restrict__ qkv,
                              bf16* __restrict__ qh, bf16* __restrict__ ql) {
    int rowid = blockIdx.x;  // t*HH + h
    int d = threadIdx.x;
    int t = rowid >> 3, hh = rowid & 7;
    __shared__ float sh[HDIM];
    sh[d] = qkv[(size_t)t * NQKV + hh * HDIM + d];
    __syncthreads();
    int pos = t & (SS - 1);
    int i = d & 63;
    float invf = expf(-13.815510557964274f * ((float)(2 * i) * (1.0f / HDIM)));
    float f = (float)pos * invf;
    float c = cosf(f), sn = sinf(f);
    float v = (d < 64) ? (sh[d] * c - sh[d + 64] * sn)
                       : (sh[d] * c + sh[d - 64] * sn);
    bf16 h, l; split_bf(v, h, l);
    qh[(size_t)rowid * HDIM + d] = h;
    ql[(size_t)rowid * HDIM + d] = l;
}

// ---------------- kv quant: k -> quant+rope -> hi/lo; v -> integer + scale ------
__global__ void quant_k_kernel(const float* __restrict__ qkv,
                               bf16* __restrict__ kh, bf16* __restrict__ kl) {
    int rowid = blockIdx.x;  // t*KV + kvh
    int d = threadIdx.x;
    int t = rowid >> 1, kvh = rowid & 1;
    float v = qkv[(size_t)t * NQKV + 1024 + kvh * HDIM + d];
    __shared__ float smn[HDIM], smx[HDIM], sh[HDIM];
    smn[d] = v; smx[d] = v; __syncthreads();
    for (int o2 = 64; o2; o2 >>= 1) {
        if (d < o2) {
            smn[d] = fminf(smn[d], smn[d + o2]);
            smx[d] = fmaxf(smx[d], smx[d + o2]);
        }
        __syncthreads();
    }
    float scale = fmaxf(smx[0] - smn[0], 1e-5f) / 15.0f;
    float base = fminf(fmaxf(rintf(-smn[0] / scale), 0.f), 15.f);
    float q = (fminf(fmaxf(rintf(v / scale) + base, 0.f), 15.f) - base) * scale;
    sh[d] = q; __syncthreads();
    int pos = t & (SS - 1);
    int i = d & 63;
    float invf = expf(-13.815510557964274f * ((float)(2 * i) * (1.0f / HDIM)));
    float f = (float)pos * invf;
    float c = cosf(f), sn = sinf(f);
    q = (d < 64) ? (sh[d] * c - sh[d + 64] * sn)
                 : (sh[d] * c + sh[d - 64] * sn);
    bf16 h, l; split_bf(q, h, l);
    kh[(size_t)rowid * HDIM + d] = h;
    kl[(size_t)rowid * HDIM + d] = l;
}

__global__ void quant_v_kernel(const float* __restrict__ qkv,
                               bf16* __restrict__ vn, float* __restrict__ vs) {
    int rowid = blockIdx.x;
    int d = threadIdx.x;
    int t = rowid >> 1, kvh = rowid & 1;
    float v = qkv[(size_t)t * NQKV + 1280 + kvh * HDIM + d];
    __shared__ float smn[HDIM], smx[HDIM];
    smn[d] = v; smx[d] = v; __syncthreads();
    for (int o2 = 64; o2; o2 >>= 1) {
        if (d < o2) {
            smn[d] = fminf(smn[d], smn[d + o2]);
            smx[d] = fmaxf(smx[d], smx[d + o2]);
        }
        __syncthreads();
    }
    float scale = fmaxf(smx[0] - smn[0], 1e-5f) / 15.0f;
    float base = fminf(fmaxf(rintf(-smn[0] / scale), 0.f), 15.f);
    float q = fminf(fmaxf(rintf(v / scale) + base, 0.f), 15.f) - base;  // integer
    vn[(size_t)rowid * HDIM + d] = __float2bfloat16(q);
    if (d == 0) vs[rowid] = scale;
}

// ---------------- TC scores: S = q k^T / sqrt(HD), bf16x3, causal skip ---------
__global__ __launch_bounds__(256, 1) void scores_tc(
    const bf16* __restrict__ qh, const bf16* __restrict__ ql,
    const bf16* __restrict__ kh, const bf16* __restrict__ kl,
    float* __restrict__ sc)
{
    int z = blockIdx.z;
    int m0 = blockIdx.y * 128, n0 = blockIdx.x * 128;
    if (n0 > m0) return;
    int b = z >> 3, hh = z & 7, kvh = (z & 7) >> 2;
    int tid = threadIdx.x, wid = tid >> 5, lid = tid & 31;
    extern __shared__ char smem[];
    uint32_t sb = smem_u32(smem);

    const bf16* src[16]; uint32_t dst[16];
    #pragma unroll
    for (int ci = 0; ci < 16; ci++) {
        int gid = ci * 256 + tid;
        int t4 = gid >> 10;  // 0:qh 1:ql 2:kh 3:kl
        int r = (gid >> 3) & 127;
        int c8 = gid & 7;
        const bf16* p;
        if (t4 == 0)      p = qh + ((size_t)(b * SS + m0 + r) * HH + hh) * HDIM;
        else if (t4 == 1) p = ql + ((size_t)(b * SS + m0 + r) * HH + hh) * HDIM;
        else if (t4 == 2) p = kh + ((size_t)(b * SS + n0 + r) * KV + kvh) * HDIM;
        else              p = kl + ((size_t)(b * SS + n0 + r) * KV + kvh) * HDIM;
        src[ci] = p + c8 * 8;
        dst[ci] = (uint32_t)(t4 * TILE_BYTES) + swz((uint32_t)(r * 128 + c8 * 16));
    }
    // stage 0 (k=0..63), stage 1 (k=64..127)
    #pragma unroll
    for (int ci = 0; ci < 16; ci++) cpa16(sb + dst[ci], src[ci]);
    cpa_commit();
    #pragma unroll
    for (int ci = 0; ci < 16; ci++) cpa16(sb + 4 * TILE_BYTES + dst[ci], src[ci] + 64);
    cpa_commit();

    int wr = (wid & 3) * 32;
    int wc = (wid >> 2) * 64;
    int rowm = (lid & 7) + ((lid >> 3) & 1) * 8;
    int colb = (lid >> 4) * 16;
    float acc[2][8][4] = {};

    #pragma unroll 1
    for (int ch = 0; ch < 2; ch++) {
        if (ch == 0) cpa_wait1(); else cpa_wait0();
        __syncthreads();
        uint32_t base = sb + ch * 4 * TILE_BYTES;
        #pragma unroll
        for (int s16 = 0; s16 < 4; s16++) {
            int kb0 = s16 * 32 + colb;
            uint32_t ah[2][4], al[2][4], bh[8][2], bl[8][2];
            #pragma unroll
            for (int i = 0; i < 2; i++) {
                uint32_t off = (uint32_t)((wr + i * 16 + rowm) * 128 + kb0);
                ldsm4(base + swz(off), ah[i][0], ah[i][1], ah[i][2], ah[i][3]);
                ldsm4(base + TILE_BYTES + swz(off), al[i][0], al[i][1], al[i][2], al[i][3]);
            }
            #pragma unroll
            for (int j = 0; j < 4; j++) {
                uint32_t off = (uint32_t)((wc + j * 16 + rowm) * 128 + kb0);
                uint32_t r0, r1, r2, r3;
                ldsm4(base + 2 * TILE_BYTES + swz(off), r0, r1, r2, r3);
                bh[j * 2][0] = r0; bh[j * 2][1] = r2;
                bh[j * 2 + 1][0] = r1; bh[j * 2 + 1][1] = r3;
                ldsm4(base + 3 * TILE_BYTES + swz(off), r0, r1, r2, r3);
                bl[j * 2][0] = r0; bl[j * 2][1] = r2;
                bl[j * 2 + 1][0] = r1; bl[j * 2 + 1][1] = r3;
            }
            #pragma unroll
            for (int i = 0; i < 2; i++)
                #pragma unroll
                for (int jn = 0; jn < 8; jn++) {
                    mma16816(acc[i][jn], ah[i], bh[jn]);
                    mma16816(acc[i][jn], ah[i], bl[jn]);
                    mma16816(acc[i][jn], al[i], bh[jn]);
                }
        }
    }
    const float scalef = 0.08838834764831845f;
    float* C = sc + (size_t)z * SS * SS;
    #pragma unroll
    for (int i = 0; i < 2; i++)
        #pragma unroll
        for (int jn = 0; jn < 8; jn++) {
            int r0 = m0 + wr + i * 16 + (lid >> 2);
            int cc = n0 + wc + jn * 8 + (lid & 3) * 2;
            #pragma unroll
            for (int half = 0; half < 2; half++) {
                int row = r0 + half * 8;
                float v0 = acc[i][jn][half * 2 + 0] * scalef;
                float v1 = acc[i][jn][half * 2 + 1] * scalef;
                *reinterpret_cast<float2*>(C + (size_t)row * SS + cc) = make_float2(v0, v1);
            }
        }
}

// ---------------- softmax: fp32 scores -> (p * vscale) split to bf16 hi/lo -----
__global__ void softmax_kernel(float* __restrict__ sc, const float* __restrict__ vs,
                               bf16* __restrict__ ph, bf16* __restrict__ pl) {
    int r = blockIdx.x;
    int z = r >> 10;
    int s = r & (SS - 1);
    int b = z >> 3, kvh = (z & 7) >> 2;
    float* row = sc + (size_t)r * SS;
    int n = s + 1;
    __shared__ float sh[256];
    float m = -INFINITY;
    for (int i = threadIdx.x; i < n; i += 256) m = fmaxf(m, row[i]);
    sh[threadIdx.x] = m; __syncthreads();
    for (int o2 = 128; o2; o2 >>= 1) {
        if (threadIdx.x < o2) sh[threadIdx.x] = fmaxf(sh[threadIdx.x], sh[threadIdx.x + o2]);
        __syncthreads();
    }
    m = sh[0]; __syncthreads();
    float sum = 0.f;
    for (int i = threadIdx.x; i < n; i += 256) {
        float e = expf(row[i] - m);
        row[i] = e; sum += e;
    }
    sh[threadIdx.x] = sum; __syncthreads();
    for (int o2 = 128; o2; o2 >>= 1) {
        if (threadIdx.x < o2) sh[threadIdx.x] += sh[threadIdx.x + o2];
        __syncthreads();
    }
    float inv = 1.0f / sh[0];
    for (int i = threadIdx.x; i < SS; i += 256) {
        float p = (i < n) ? row[i] * inv : 0.f;
        float pv = p * vs[(size_t)((b * SS + i) * KV + kvh)];
        bf16 h, l; split_bf(pv, h, l);
        ph[(size_t)r * SS + i] = h;
        pl[(size_t)r * SS + i] = l;
    }
}

// ---------------- TC AV: O = P' @ N_v (exact integer V), split output ----------
__global__ __launch_bounds__(256, 1) void av_tc(
    const bf16* __restrict__ ph, const bf16* __restrict__ pl,
    const bf16* __restrict__ vn, bf16* __restrict__ oh, bf16* __restrict__ ol)
{
    int z = blockIdx.z;
    int b = z >> 3, hh = z & 7, kvh = (z & 7) >> 2;
    int m0 = blockIdx.y * 128;
    int tid = threadIdx.x, wid = tid >> 5, lid = tid & 31;
    extern __shared__ char smem[];
    uint32_t sb = smem_u32(smem);

    // per-thread slots: Ph 4, Pl 4, V 4 (V stored as 2 planes of [64][128B])
    const bf16* srcP[4]; const bf16* srcV[4];
    uint32_t dstP[4], dstV[4];
    ptrdiff_t dpl = pl - ph;
    #pragma unroll
    for (int ci = 0; ci < 4; ci++) {
        int gid = ci * 256 + tid;
        int r = (gid >> 3) & 127;
        int c8 = gid & 7;
        srcP[ci] = ph + (size_t)z * SS * SS + (size_t)(m0 + r) * SS + c8 * 8;
        dstP[ci] = swz((uint32_t)(r * 128 + c8 * 16));
        int gid2 = 2048 + gid;  // V: 1024 chunks => vrow 64 x c16 16
        int vrow = (gid2 >> 4) & 63;
        int c16 = gid2 & 15;
        int plane = c16 >> 3, cc8 = c16 & 7;
        srcV[ci] = vn + ((size_t)(b * SS + vrow) * KV + kvh) * HDIM + plane * 64 + cc8 * 8;
        dstV[ci] = (uint32_t)(2 * TILE_BYTES + plane * 8192) + swz((uint32_t)(vrow * 128 + cc8 * 16));
    }

    int n_ch = (m0 >> 6) + 2;
    #pragma unroll 1
    for (int p = 0; p < 2 && p < n_ch; p++) {
        uint32_t base = sb + p * AV_STAGE;
        #pragma unroll
        for (int ci = 0; ci < 4; ci++) {
            size_t ko = (size_t)p * KT;
            cpa16(base + dstP[ci], srcP[ci] + ko);
            cpa16(base + TILE_BYTES + dstP[ci], srcP[ci] + dpl + ko);
            cpa16(base + dstV[ci], srcV[ci] + ko * (KV * HDIM));
        }
        cpa_commit();
    }

    int wr = (wid & 3) * 32;
    int wc = (wid >> 2) * 64;      // 0 or 64 -> plane
    int vplane = wc >> 6;
    int rowm = (lid & 7) + ((lid >> 3) & 1) * 8;
    int colb = (lid >> 4) * 16;
    float acc[2][8][4] = {};

    #pragma unroll 1
    for (int kt = 0; kt < n_ch; kt++) {
        cpa_wait1();
        __syncthreads();
        if (kt + 2 < n_ch) {
            int sl = (kt + 2) % 3;
            uint32_t base = sb + sl * AV_STAGE;
            size_t ko = (size_t)(kt + 2) * KT;
            #pragma unroll
            for (int ci = 0; ci < 4; ci++) {
                cpa16(base + dstP[ci], srcP[ci] + ko);
                cpa16(base + TILE_BYTES + dstP[ci], srcP[ci] + dpl + ko);
                cpa16(base + dstV[ci], srcV[ci] + ko * (KV * HDIM));
            }
            cpa_commit();
        }
        uint32_t sbase = sb + (kt % 3) * AV_STAGE;
        uint32_t vbase = sbase + 2 * TILE_BYTES + vplane * 8192;
        #pragma unroll
        for (int s16 = 0; s16 < 4; s16++) {
            int kb0 = s16 * 32 + colb;
            uint32_t ah[2][4], al[2][4], bv[8][2];
            #pragma unroll
            for (int i = 0; i < 2; i++) {
                uint32_t off = (uint32_t)((wr + i * 16 + rowm) * 128 + kb0);
                ldsm4(sbase + swz(off), ah[i][0], ah[i][1], ah[i][2], ah[i][3]);
                ldsm4(sbase + TILE_BYTES + swz(off), al[i][0], al[i][1], al[i][2], al[i][3]);
            }
            #pragma unroll
            for (int j16 = 0; j16 < 4; j16++) {
                uint32_t krow = (uint32_t)(s16 * 16 + (lid & 7) + 8 * ((lid >> 3) & 1));
                uint32_t off = krow * 128 + (uint32_t)(j16 * 32 + 16 * (lid >> 4));
                uint32_t r0, r1, r2, r3;
                ldsm4t(vbase + swz(off), r0, r1, r2, r3);
                bv[j16 * 2][0] = r0; bv[j16 * 2][1] = r1;
                bv[j16 * 2 + 1][0] = r2; bv[j16 * 2 + 1][1] = r3;
            }
            #pragma unroll
            for (int i = 0; i < 2; i++)
                #pragma unroll
                for (int jn = 0; jn < 8; jn++) {
                    mma16816(acc[i][jn], ah[i], bv[jn]);
                    mma16816(acc[i][jn], al[i], bv[jn]);
                }
        }
    }

    #pragma unroll
    for (int i = 0; i < 2; i++)
        #pragma unroll
        for (int jn = 0; jn < 8; jn++) {
            int r0 = m0 + wr + i * 16 + (lid >> 2);
            int cc = wc + jn * 8 + (lid & 3) * 2;
            #pragma unroll
            for (int half = 0; half < 2; half++) {
                int row = r0 + half * 8;
                float v0 = acc[i][jn][half * 2 + 0];
                float v1 = acc[i][jn][half * 2 + 1];
                size_t o = ((size_t)(b * SS + row) * HH + hh) * HDIM + cc;
                bf16 h0, l0, h1, l1;
                split_bf(v0, h0, l0); split_bf(v1, h1, l1);
                oh[o] = h0; oh[o + 1] = h1;
                ol[o] = l0; ol[o + 1] = l1;
            }
        }
}

// ---------------- router ----------------
__global__ __launch_bounds__(256) void router_kernel(
    const float* __restrict__ hn, const float* __restrict__ wg)
{
    int tkn = blockIdx.x;
    int w = threadIdx.x >> 5, lane = threadIdx.x & 31;
    const float* x = hn + (size_t)tkn * DD;
    const float* g = wg + (size_t)w * DD;
    float s = 0.f;
    for (int i = lane; i < DD; i += 32) s += x[i] * g[i];
    s = warp_sum(s);
    __shared__ float lg[EE];
    if (lane == 0) lg[w] = s;
    __syncthreads();
    if (threadIdx.x == 0) {
        float m = -INFINITY;
        #pragma unroll
        for (int e = 0; e < EE; e++) m = fmaxf(m, lg[e]);
        float ex[EE];
        #pragma unroll
        for (int e = 0; e < EE; e++) ex[e] = expf(lg[e] - m);
        int i1 = 0; float m1 = ex[0];
        #pragma unroll
        for (int e = 1; e < EE; e++) if (ex[e] > m1) { m1 = ex[e]; i1 = e; }
        int i2 = -1; float m2 = -1.f;
        #pragma unroll
        for (int e = 0; e < EE; e++) if (e != i1 && ex[e] > m2) { m2 = ex[e]; i2 = e; }
        float inv = 1.0f / (m1 + m2);
        int p1 = atomicAdd(&g_cnt[i1], 1);
        g_tok[i1 * TT + p1] = tkn; g_twt[i1 * TT + p1] = m1 * inv;
        int p2 = atomicAdd(&g_cnt[i2], 1);
        g_tok[i2 * TT + p2] = tkn; g_twt[i2 * TT + p2] = m2 * inv;
    }
}

__global__ void final_add_kernel(const float* __restrict__ h, const float* __restrict__ moe,
                                 float* __restrict__ out) {
    int i = blockIdx.x * 256 + threadIdx.x;
    out[i] = h[i] + moe[i];
}

// ======================= host =======================
extern "C" void kernel_launch(void* const* d_in, const int* in_sizes, int n_in,
                              void* d_out, int out_size) {
    const float* hidden = (const float*)d_in[0];
    const float* w_q    = (const float*)d_in[1];
    const float* w_k    = (const float*)d_in[2];
    const float* w_v    = (const float*)d_in[3];
    const float* w_o    = (const float*)d_in[4];
    const float* g1     = (const float*)d_in[5];
    const float* g2     = (const float*)d_in[6];
    const float* w_gate = (const float*)d_in[7];
    const float* w1     = (const float*)d_in[8];
    const float* w3     = (const float*)d_in[9];
    const float* w2     = (const float*)d_in[10];
    float* out = (float*)d_out;

    bf16 *p_wqkvn, *p_won, *p_w1n, *p_w3n, *p_w2n;
    float *p_wqkvs, *p_wos, *p_w1s, *p_w3s, *p_w2s;
    bf16 *p_xnh, *p_xnl, *p_hnh, *p_hnl, *p_oh, *p_ol, *p_uph, *p_upl;
    bf16 *p_qh, *p_ql, *p_kh, *p_kl, *p_vn, *p_ph, *p_pl;
    float *p_qkv, *p_vs, *p_sc, *p_h, *p_hn, *p_up1, *p_moe, *p_twt;
    int *p_cnt, *p_tok;
    cudaGetSymbolAddress((void**)&p_wqkvn, g_wqkvn); cudaGetSymbolAddress((void**)&p_wqkvs, g_wqkvs);
    cudaGetSymbolAddress((void**)&p_won, g_won); cudaGetSymbolAddress((void**)&p_wos, g_wos);
    cudaGetSymbolAddress((void**)&p_w1n, g_w1n); cudaGetSymbolAddress((void**)&p_w1s, g_w1s);
    cudaGetSymbolAddress((void**)&p_w3n, g_w3n); cudaGetSymbolAddress((void**)&p_w3s, g_w3s);
    cudaGetSymbolAddress((void**)&p_w2n, g_w2n); cudaGetSymbolAddress((void**)&p_w2s, g_w2s);
    cudaGetSymbolAddress((void**)&p_xnh, g_xnh); cudaGetSymbolAddress((void**)&p_xnl, g_xnl);
    cudaGetSymbolAddress((void**)&p_hnh, g_hnh); cudaGetSymbolAddress((void**)&p_hnl, g_hnl);
    cudaGetSymbolAddress((void**)&p_oh, g_oh);   cudaGetSymbolAddress((void**)&p_ol, g_ol);
    cudaGetSymbolAddress((void**)&p_uph, g_uph); cudaGetSymbolAddress((void**)&p_upl, g_upl);
    cudaGetSymbolAddress((void**)&p_qkv, g_qkv);
    cudaGetSymbolAddress((void**)&p_qh, g_qh);   cudaGetSymbolAddress((void**)&p_ql, g_ql);
    cudaGetSymbolAddress((void**)&p_kh, g_kh);   cudaGetSymbolAddress((void**)&p_kl, g_kl);
    cudaGetSymbolAddress((void**)&p_vn, g_vn);   cudaGetSymbolAddress((void**)&p_vs, g_vs);
    cudaGetSymbolAddress((void**)&p_sc, g_sc);
    cudaGetSymbolAddress((void**)&p_ph, g_ph);   cudaGetSymbolAddress((void**)&p_pl, g_pl);
    cudaGetSymbolAddress((void**)&p_h, g_h);
    cudaGetSymbolAddress((void**)&p_hn, g_hn);   cudaGetSymbolAddress((void**)&p_up1, g_up1);
    cudaGetSymbolAddress((void**)&p_moe, g_moe);
    cudaGetSymbolAddress((void**)&p_cnt, g_cnt); cudaGetSymbolAddress((void**)&p_tok, g_tok);
    cudaGetSymbolAddress((void**)&p_twt, g_twt);

    cudaFuncSetAttribute(gemm_tc<0>, cudaFuncAttributeMaxDynamicSharedMemorySize, SMEM_SZ);
    cudaFuncSetAttribute(gemm_tc<1>, cudaFuncAttributeMaxDynamicSharedMemorySize, SMEM_SZ);
    cudaFuncSetAttribute(gemm_tc<2>, cudaFuncAttributeMaxDynamicSharedMemorySize, SMEM_SZ);
    cudaFuncSetAttribute(gemm_tc<3>, cudaFuncAttributeMaxDynamicSharedMemorySize, SMEM_SZ);
    cudaFuncSetAttribute(gemm_tc<4>, cudaFuncAttributeMaxDynamicSharedMemorySize, SMEM_SZ);
    cudaFuncSetAttribute(scores_tc, cudaFuncAttributeMaxDynamicSharedMemorySize, SCR_SMEM);
    cudaFuncSetAttribute(av_tc, cudaFuncAttributeMaxDynamicSharedMemorySize, AV_SMEM);

    zero_kernel<<<8192, 256>>>(p_moe, p_cnt);

    quantw_kernel<<<1024, 256>>>(w_q, p_wqkvn, p_wqkvs, DD * DD / 128);
    quantw_kernel<<<256, 256>>>(w_k, p_wqkvn + 1024 * DD, p_wqkvs + 1024 * 8, KV * HDIM * DD / 128);
    quantw_kernel<<<256, 256>>>(w_v, p_wqkvn + 1280 * DD, p_wqkvs + 1280 * 8, KV * HDIM * DD / 128);
    quantw_kernel<<<1024, 256>>>(w_o, p_won, p_wos, DD * DD / 128);
    quantw_kernel<<<28672, 256>>>(w1, p_w1n, p_w1s, EE * FFND * DD / 128);
    quantw_kernel<<<28672, 256>>>(w3, p_w3n, p_w3s, EE * FFND * DD / 128);
    quantw_kernel<<<28672, 256>>>(w2, p_w2n, p_w2s, EE * DD * FFND / 128);

    // ---- attention ----
    rms_split_kernel<false><<<TT, 256>>>(hidden, g1, nullptr, p_xnh, p_xnl);
    gemm_tc<0><<<dim3(12, 16, 1), 256, SMEM_SZ>>>(p_xnh, p_xnl, DD, 0,
        p_wqkvn, p_wqkvs, DD, 0, 0,
        p_qkv, nullptr, nullptr, NQKV, 0, TT, nullptr, DD, nullptr, nullptr, nullptr);
    rope_q_kernel<<<TT * HH, HDIM>>>(p_qkv, p_qh, p_ql);
    quant_k_kernel<<<TT * KV, HDIM>>>(p_qkv, p_kh, p_kl);
    quant_v_kernel<<<TT * KV, HDIM>>>(p_qkv, p_vn, p_vs);
    scores_tc<<<dim3(8, 8, BB * HH), 256, SCR_SMEM>>>(p_qh, p_ql, p_kh, p_kl, p_sc);
    softmax_kernel<<<BB * HH * SS, 256>>>(p_sc, p_vs, p_ph, p_pl);
    av_tc<<<dim3(1, 8, BB * HH), 256, AV_SMEM>>>(p_ph, p_pl, p_vn, p_oh, p_ol);
    gemm_tc<1><<<dim3(8, 16, 1), 256, SMEM_SZ>>>(p_oh, p_ol, DD, 0,
        p_won, p_wos, DD, 0, 0,
        p_h, nullptr, nullptr, DD, 0, TT, nullptr, DD, hidden, nullptr, nullptr);

    // ---- MoE ----
    rms_split_kernel<true><<<TT, 256>>>(p_h, g2, p_hn, p_hnh, p_hnl);
    router_kernel<<<TT, 256>>>(p_hn, w_gate);
    gemm_tc<2><<<dim3(28, 16, EE), 256, SMEM_SZ>>>(p_hnh, p_hnl, DD, 0,
        p_w1n, p_w1s, DD, (size_t)FFND * DD, (size_t)FFND * (DD / 128),
        p_up1, nullptr, nullptr, FFND, (size_t)TT * FFND,
        0, p_cnt, DD, nullptr, p_tok, nullptr);
    gemm_tc<4><<<dim3(28, 16, EE), 256, SMEM_SZ>>>(p_hnh, p_hnl, DD, 0,
        p_w3n, p_w3s, DD, (size_t)FFND * DD, (size_t)FFND * (DD / 128),
        nullptr, p_uph, p_upl, FFND, (size_t)TT * FFND,
        0, p_cnt, DD, p_up1, p_tok, nullptr);
    gemm_tc<3><<<dim3(8, 16, EE), 256, SMEM_SZ>>>(p_uph, p_upl, FFND, (size_t)TT * FFND,
        p_w2n, p_w2s, FFND, (size_t)DD * FFND, (size_t)DD * (FFND / 128),
        p_moe, nullptr, nullptr, DD, 0,
        0, p_cnt, FFND, nullptr, p_tok, p_twt);
    final_add_kernel<<<8192, 256>>>(p_h, p_moe, out);
}